// round 13
// baseline (speedup 1.0000x reference)
#include <cuda_runtime.h>
#include <cuda_bf16.h>
#include <math.h>
#include <stdint.h>

#define BBATCH 64
#define NQD    32
#define NDD    512
#define DINF   64
#define DDF    128
#define KKN    16
#define NDN    (BBATCH*NDD)      // 32768
#define NQN    (BBATCH*NQD)      // 2048
#define NALL   (NDN+NQN)         // 34816
#define EDM    (NDN*8)           // 262144
#define EQM    (NQN*8)           // 16384
#define EALL   (EDM+EQM)         // 278528
#define ATTS   ((size_t)BBATCH*NQD*NDD)
#define QWS    ((size_t)BBATCH*512*DDF)

// ------------------------- static device scratch ----------------------------
__device__ float g_dinv[NALL];
__device__ int   g_indeg[NALL];
__device__ int   g_rows[NALL];
__device__ int   g_fill[NALL];
__device__ int   g_cols[EALL];
__device__ float g_vals[EALL];
__device__ float g_xw[(size_t)NALL*DDF];
__device__ float g_att3[3*ATTS];
__device__ float g_lq3[3*NQN*KKN];
__device__ float g_ld3[3*NDN*KKN];
__device__ float g_e1[ATTS];
__device__ float g_e3[ATTS];
__device__ float g_acc[ATTS];
__device__ float g_accB[ATTS];
__device__ float g_wk[128];
__device__ __nv_bfloat16 g_hallh[(size_t)3*NALL*DDF];
__device__ __nv_bfloat16 g_halll[(size_t)3*NALL*DDF];
__device__ __nv_bfloat16 g_qwh3[3*QWS];
__device__ __nv_bfloat16 g_qwl3[3*QWS];
__device__ __nv_bfloat16 g_xh[(size_t)NALL*DDF], g_xl[(size_t)NALL*DDF];
__device__ __nv_bfloat16 g_w1th[DDF*DDF], g_w1tl[DDF*DDF];
__device__ __nv_bfloat16 g_w2th[DDF*DDF], g_w2tl[DDF*DDF];
__device__ __nv_bfloat16 g_w3th[DDF*DDF], g_w3tl[DDF*DDF];
__device__ __nv_bfloat16 g_wnth[(size_t)3*KKN*DDF*DDF], g_wntl[(size_t)3*KKN*DDF*DDF];

// --------------------------- PTX helpers -------------------------------------
__device__ __forceinline__ uint32_t smem_u32(const void* p) {
    uint32_t a;
    asm("{ .reg .u64 t; cvta.to.shared.u64 t, %1; cvt.u32.u64 %0, t; }" : "=r"(a) : "l"(p));
    return a;
}
#define LDSM_X4(r, a) \
    asm volatile("ldmatrix.sync.aligned.m8n8.x4.shared.b16 {%0,%1,%2,%3}, [%4];" \
        : "=r"((r)[0]), "=r"((r)[1]), "=r"((r)[2]), "=r"((r)[3]) : "r"(a))
#define LDSM_X2(r, a) \
    asm volatile("ldmatrix.sync.aligned.m8n8.x2.shared.b16 {%0,%1}, [%2];" \
        : "=r"((r)[0]), "=r"((r)[1]) : "r"(a))
#define MMA16816(d, a, b) \
    asm volatile("mma.sync.aligned.m16n8k16.row.col.f32.bf16.bf16.f32 " \
        "{%0,%1,%2,%3},{%4,%5,%6,%7},{%8,%9},{%0,%1,%2,%3};" \
        : "+f"((d)[0]), "+f"((d)[1]), "+f"((d)[2]), "+f"((d)[3]) \
        : "r"((a)[0]), "r"((a)[1]), "r"((a)[2]), "r"((a)[3]), "r"((b)[0]), "r"((b)[1]))

// =================== fused prep: weights + inputs + wk + zero ================
__global__ void prep_all(
    const float* __restrict__ W1, const float* __restrict__ W2, const float* __restrict__ W3,
    const float* __restrict__ Wn1, const float* __restrict__ Wn2, const float* __restrict__ Wn3,
    const float* __restrict__ x_d, const float* __restrict__ x_q,
    const float* __restrict__ cw1, const float* __restrict__ cw2, const float* __restrict__ cw3,
    const float* __restrict__ w_end,
    __nv_bfloat16* __restrict__ w1th, __nv_bfloat16* __restrict__ w1tl,
    __nv_bfloat16* __restrict__ w2th, __nv_bfloat16* __restrict__ w2tl,
    __nv_bfloat16* __restrict__ w3th, __nv_bfloat16* __restrict__ w3tl,
    __nv_bfloat16* __restrict__ wnth, __nv_bfloat16* __restrict__ wntl,
    __nv_bfloat16* __restrict__ xh, __nv_bfloat16* __restrict__ xl,
    float* __restrict__ wk, int* __restrict__ indeg, int* __restrict__ fill) {
    __shared__ float ts[32][33];
    const int blk = blockIdx.x, tid = threadIdx.x;
    if (blk < 800) {
        const float* src; __nv_bfloat16 *oh, *ol; int k, t2;
        if (blk < 16)      { src = W2; oh = w2th; ol = w2tl; k = 0; t2 = blk; }
        else if (blk < 32) { src = W3; oh = w3th; ol = w3tl; k = 0; t2 = blk - 16; }
        else {
            int t = blk - 32, l = t >> 8, rem = t & 255;
            k = rem >> 4; t2 = rem & 15;
            src = (l == 0) ? Wn1 : (l == 1) ? Wn2 : Wn3;
            oh = wnth + (size_t)l * 2048 * 128; ol = wntl + (size_t)l * 2048 * 128;
        }
        int e0 = (t2 & 3) * 32, d0 = (t2 >> 2) * 32;
        int tx = tid & 31, ty = tid >> 5;
        const float* ink = src + (size_t)k * 16384;
#pragma unroll
        for (int j = 0; j < 32; j += 8)
            ts[ty + j][tx] = ink[(size_t)(d0 + ty + j) * 128 + e0 + tx];
        __syncthreads();
#pragma unroll
        for (int j = 0; j < 32; j += 8) {
            float v = ts[tx][ty + j];
            size_t o = ((size_t)k * 128 + e0 + ty + j) * 128 + d0 + tx;
            __nv_bfloat16 h = __float2bfloat16(v);
            oh[o] = h;
            ol[o] = __float2bfloat16(v - __bfloat162float(h));
        }
    } else if (blk < 864) {
        int i = (blk - 800) * 256 + tid;
        int e = i >> 7, d = i & 127;
        float v = (d < 64) ? W1[d * 128 + e] : 0.f;
        __nv_bfloat16 h = __float2bfloat16(v);
        w1th[i] = h;
        w1tl[i] = __float2bfloat16(v - __bfloat162float(h));
    } else if (blk < 864 + 8192) {
        int i = (blk - 864) * 256 + tid;
        int node = i >> 6, c = i & 63;
        float v = x_d[i];
        __nv_bfloat16 h = __float2bfloat16(v);
        size_t o = (size_t)node * 128 + c;
        xh[o] = h; xl[o] = __float2bfloat16(v - __bfloat162float(h));
        xh[o + 64] = __float2bfloat16(0.f);
        xl[o + 64] = __float2bfloat16(0.f);
    } else if (blk < 864 + 8192 + 512) {
        int i = (blk - 864 - 8192) * 256 + tid;
        int node = NDN + (i >> 6), c = i & 63;
        float v = x_q[i];
        __nv_bfloat16 h = __float2bfloat16(v);
        size_t o = (size_t)node * 128 + c;
        xh[o] = h; xl[o] = __float2bfloat16(v - __bfloat162float(h));
        xh[o + 64] = __float2bfloat16(0.f);
        xl[o + 64] = __float2bfloat16(0.f);
    } else if (blk == 9568) {
        int k = tid;
        if (k < 16) {
            wk[k]      = cw1[k];                              wk[16 + k] = 0.f;
            wk[32 + k] = w_end[1] * cw2[k] + w_end[19 + k];   wk[48 + k] = 0.f;
            wk[64 + k] = cw3[k];
            wk[80 + k] = w_end[3 + k] + w_end[35 + k];
        }
        if (k == 0) { wk[96] = w_end[0]; wk[97] = w_end[2]; }
    } else {
        int i = (blk - 9569) * 256 + tid;
        if (i < NALL) { indeg[i] = 0; fill[i] = 0; }
    }
}

// ------------------------------ CSR build (combined) -------------------------
__global__ void count_all_kern(const int* __restrict__ dst_d, const int* __restrict__ dst_q,
                               int* __restrict__ indeg) {
    int i = blockIdx.x * blockDim.x + threadIdx.x;
    if (i < EDM) atomicAdd(&indeg[dst_d[i]], 1);
    else if (i < EALL) atomicAdd(&indeg[dst_q[i - EDM] + NDN], 1);
}
__global__ void scan_dinv_kern(const int* __restrict__ indeg, int* __restrict__ rows,
                               float* __restrict__ dinv) {
    __shared__ int s[512];
    int g = blockIdx.x, t = threadIdx.x;
    int nper, nodebase, ebase;
    if (g < 64) { nper = 512; nodebase = g * 512; ebase = g * 4096; }
    else        { nper = 32;  nodebase = NDN + (g - 64) * 32; ebase = EDM + (g - 64) * 256; }
    int v = (t < nper) ? indeg[nodebase + t] : 0;
    s[t] = v; __syncthreads();
    for (int off = 1; off < 512; off <<= 1) {
        int x = (t >= off) ? s[t - off] : 0;
        __syncthreads();
        s[t] += x;
        __syncthreads();
    }
    if (t < nper) {
        rows[nodebase + t] = ebase + s[t] - v;
        dinv[nodebase + t] = rsqrtf((float)v + 1.0f);
    }
}
__global__ void fill_all_kern(const int* __restrict__ src_d, const int* __restrict__ dst_d,
                              const int* __restrict__ src_q, const int* __restrict__ dst_q,
                              const float* __restrict__ dinv, const int* __restrict__ rows,
                              int* __restrict__ fill, int* __restrict__ cols,
                              float* __restrict__ vals) {
    int i = blockIdx.x * blockDim.x + threadIdx.x;
    int s, t;
    if (i < EDM) { s = src_d[i]; t = dst_d[i]; }
    else if (i < EALL) { int j = i - EDM; s = src_q[j] + NDN; t = dst_q[j] + NDN; }
    else return;
    int p = atomicAdd(&fill[t], 1);
    int idx = rows[t] + p;
    cols[idx] = s;
    vals[idx] = dinv[s] * dinv[t];
}

// ------ GCN aggregation: lane-parallel index prefetch + 4-way batched gather -
__global__ void spmm_gcn(const float* __restrict__ h, const int* __restrict__ rows,
                         const int* __restrict__ cols, const float* __restrict__ vals,
                         const int* __restrict__ indeg, const float* __restrict__ dinv,
                         const float* __restrict__ bias,
                         __nv_bfloat16* __restrict__ oh, __nv_bfloat16* __restrict__ ol,
                         const float* __restrict__ Vn,
                         float* __restrict__ lq, float* __restrict__ ld, int N) {
    const unsigned FULL = 0xffffffffu;
    int t = blockIdx.x * blockDim.x + threadIdx.x;
    int node = t >> 5, lane = t & 31;
    if (node >= N) return;
    float di = dinv[node];
    float self = di * di;
    float4 hv = *(const float4*)(h + (size_t)node * 128 + lane * 4);
    float ax = self * hv.x, ay = self * hv.y, az = self * hv.z, aw = self * hv.w;
    int r0 = rows[node], cnt = indeg[node];
    int cnt32 = cnt < 32 ? cnt : 32;
    int myc = 0; float myw = 0.f;
    if (lane < cnt32) { myc = __ldg(&cols[r0 + lane]); myw = __ldg(&vals[r0 + lane]); }
    int e = 0;
    for (; e + 4 <= cnt32; e += 4) {
        int sA = __shfl_sync(FULL, myc, e + 0); float wA = __shfl_sync(FULL, myw, e + 0);
        int sB = __shfl_sync(FULL, myc, e + 1); float wB = __shfl_sync(FULL, myw, e + 1);
        int sC = __shfl_sync(FULL, myc, e + 2); float wC = __shfl_sync(FULL, myw, e + 2);
        int sD = __shfl_sync(FULL, myc, e + 3); float wD = __shfl_sync(FULL, myw, e + 3);
        float4 a0 = *(const float4*)(h + (size_t)sA * 128 + lane * 4);
        float4 a1 = *(const float4*)(h + (size_t)sB * 128 + lane * 4);
        float4 a2 = *(const float4*)(h + (size_t)sC * 128 + lane * 4);
        float4 a3 = *(const float4*)(h + (size_t)sD * 128 + lane * 4);
        ax += wA * a0.x; ay += wA * a0.y; az += wA * a0.z; aw += wA * a0.w;
        ax += wB * a1.x; ay += wB * a1.y; az += wB * a1.z; aw += wB * a1.w;
        ax += wC * a2.x; ay += wC * a2.y; az += wC * a2.z; aw += wC * a2.w;
        ax += wD * a3.x; ay += wD * a3.y; az += wD * a3.z; aw += wD * a3.w;
    }
    for (; e < cnt32; e++) {
        int s = __shfl_sync(FULL, myc, e); float w = __shfl_sync(FULL, myw, e);
        float4 n4 = *(const float4*)(h + (size_t)s * 128 + lane * 4);
        ax += w * n4.x; ay += w * n4.y; az += w * n4.z; aw += w * n4.w;
    }
    for (; e < cnt; e++) {
        int s = __ldg(&cols[r0 + e]);
        float w = __ldg(&vals[r0 + e]);
        float4 n4 = *(const float4*)(h + (size_t)s * 128 + lane * 4);
        ax += w * n4.x; ay += w * n4.y; az += w * n4.z; aw += w * n4.w;
    }
    float4 b4 = *(const float4*)(bias + lane * 4);
    float4 o;
    o.x = fmaxf(ax + b4.x, 0.f); o.y = fmaxf(ay + b4.y, 0.f);
    o.z = fmaxf(az + b4.z, 0.f); o.w = fmaxf(aw + b4.w, 0.f);
    __nv_bfloat162 h01 = __floats2bfloat162_rn(o.x, o.y);
    __nv_bfloat162 h23 = __floats2bfloat162_rn(o.z, o.w);
    *(__nv_bfloat162*)(oh + (size_t)node * 128 + lane * 4)     = h01;
    *(__nv_bfloat162*)(oh + (size_t)node * 128 + lane * 4 + 2) = h23;
    *(__nv_bfloat162*)(ol + (size_t)node * 128 + lane * 4) =
        __floats2bfloat162_rn(o.x - __bfloat162float(h01.x), o.y - __bfloat162float(h01.y));
    *(__nv_bfloat162*)(ol + (size_t)node * 128 + lane * 4 + 2) =
        __floats2bfloat162_rn(o.z - __bfloat162float(h23.x), o.w - __bfloat162float(h23.y));

    const float* Vrow;
    float* outp;
    if (node < NDN) { Vrow = Vn + DDF; outp = ld + (size_t)node * 16; }
    else            { Vrow = Vn;       outp = lq + (size_t)(node - NDN) * 16; }
    float res = 0.f;
#pragma unroll
    for (int k = 0; k < 16; k++) {
        float4 v4 = __ldg((const float4*)(Vrow + k * 256 + lane * 4));
        float p = o.x * v4.x + o.y * v4.y + o.z * v4.z + o.w * v4.w;
#pragma unroll
        for (int off2 = 16; off2 > 0; off2 >>= 1)
            p += __shfl_xor_sync(FULL, p, off2);
        if (lane == k) res = p;
    }
    if (lane < 16) outp[lane] = res;
}

// ======= generic split-bf16 HMMA GEMM: K split in 2 stages, 3 CTAs/SM ========
// per-stage buffers: 128 rows x 64 cols bf16, pitch 72 elems (144B)
#define HG_AH 0
#define HG_AL 18432
#define HG_BH 36864
#define HG_BL 55296
#define HG_SMEM 73728

template<int EPI>
__global__ __launch_bounds__(256) void hmma_gemm(
    const __nv_bfloat16* __restrict__ Ah, const __nv_bfloat16* __restrict__ Al,
    const __nv_bfloat16* __restrict__ Bh, const __nv_bfloat16* __restrict__ Bl,
    float* __restrict__ outF, __nv_bfloat16* __restrict__ oh,
    __nv_bfloat16* __restrict__ ol, int ldC,
    long zsA, long zsB, long zsO) {
    extern __shared__ char smem[];
    const int tid = threadIdx.x;
    const int warp = tid >> 5, lane = tid & 31;
    const int mt0 = blockIdx.y * 128, nt0 = blockIdx.x * 128;
    const long za = (long)blockIdx.z * zsA, zb = (long)blockIdx.z * zsB;
    const long zo = (long)blockIdx.z * zsO;
    __nv_bfloat16* sAh = (__nv_bfloat16*)(smem + HG_AH);
    __nv_bfloat16* sAl = (__nv_bfloat16*)(smem + HG_AL);
    __nv_bfloat16* sBh = (__nv_bfloat16*)(smem + HG_BH);
    __nv_bfloat16* sBl = (__nv_bfloat16*)(smem + HG_BL);

    const int wy = warp >> 1, wx = warp & 1;
    uint32_t sa_h = smem_u32(sAh) + ((wy * 32 + (lane & 15)) * 72 + ((lane & 16) ? 8 : 0)) * 2;
    uint32_t sa_l = sa_h + (HG_AL - HG_AH);
    uint32_t sb_h = smem_u32(sBh) + ((wx * 64 + (lane & 7)) * 72 + ((lane & 8) ? 8 : 0)) * 2;
    uint32_t sb_l = sb_h + (HG_BL - HG_BH);

    float acc[2][8][4];
#pragma unroll
    for (int mt = 0; mt < 2; mt++)
#pragma unroll
        for (int ch = 0; ch < 8; ch++)
#pragma unroll
            for (int j = 0; j < 4; j++) acc[mt][ch][j] = 0.f;

#pragma unroll 1
    for (int stage = 0; stage < 2; stage++) {
        const int k0 = stage * 64;
        if (stage) __syncthreads();
        for (int i = tid; i < 1024; i += 256) {
            int row = i >> 3, c8 = (i & 7) << 3;
            size_t g = za + ((size_t)(mt0 + row)) * 128 + k0 + c8;
            *(uint4*)(sAh + row * 72 + c8) = *(const uint4*)(Ah + g);
            *(uint4*)(sAl + row * 72 + c8) = *(const uint4*)(Al + g);
            size_t gb = zb + ((size_t)(nt0 + row)) * 128 + k0 + c8;
            *(uint4*)(sBh + row * 72 + c8) = *(const uint4*)(Bh + gb);
            *(uint4*)(sBl + row * 72 + c8) = *(const uint4*)(Bl + gb);
        }
        __syncthreads();

#pragma unroll
        for (int s = 0; s < 4; s++) {
            uint32_t RAh[2][4], RAl[2][4];
            LDSM_X4(RAh[0], sa_h + s * 32);
            LDSM_X4(RAh[1], sa_h + 2304 + s * 32);   // +16 rows * 144B
            LDSM_X4(RAl[0], sa_l + s * 32);
            LDSM_X4(RAl[1], sa_l + 2304 + s * 32);
#pragma unroll
            for (int ch = 0; ch < 8; ch++) {
                uint32_t RBh[2], RBl[2];
                LDSM_X2(RBh, sb_h + ch * 1152 + s * 32);   // 8 rows * 144B per ch
                LDSM_X2(RBl, sb_l + ch * 1152 + s * 32);
#pragma unroll
                for (int mt = 0; mt < 2; mt++) {
                    MMA16816(acc[mt][ch], RAh[mt], RBh);
                    MMA16816(acc[mt][ch], RAh[mt], RBl);
                    MMA16816(acc[mt][ch], RAl[mt], RBh);
                }
            }
        }
    }

    const int g = lane >> 2, t2 = lane & 3;
#pragma unroll
    for (int mt = 0; mt < 2; mt++) {
#pragma unroll
        for (int ch = 0; ch < 8; ch++) {
            int r = mt0 + wy * 32 + mt * 16 + g;
            int c = nt0 + wx * 64 + ch * 8 + t2 * 2;
            if (EPI == 0) {
                *(float2*)(outF + (size_t)r * ldC + c) =
                    make_float2(acc[mt][ch][0], acc[mt][ch][1]);
                *(float2*)(outF + (size_t)(r + 8) * ldC + c) =
                    make_float2(acc[mt][ch][2], acc[mt][ch][3]);
            } else {
                int kk = c >> 7, e = c & 127;
#pragma unroll
                for (int half = 0; half < 2; half++) {
                    int rr = r + half * 8;
                    int bb = rr >> 5, q = rr & 31;
                    size_t orow = zo + ((size_t)bb * 512 + q * 16 + kk) * 128 + e;
                    float v0 = acc[mt][ch][half * 2], v1 = acc[mt][ch][half * 2 + 1];
                    __nv_bfloat162 ph = __floats2bfloat162_rn(v0, v1);
                    *(__nv_bfloat162*)(oh + orow) = ph;
                    *(__nv_bfloat162*)(ol + orow) = __floats2bfloat162_rn(
                        v0 - __bfloat162float(ph.x), v1 - __bfloat162float(ph.y));
                }
            }
        }
    }
}

// ----------- attention scores via HMMA (z = level) ---------------------------
#define SC_AH 0
#define SC_AL 8704
#define SC_BH 17408
#define SC_BL 52224
#define SC_SMEM 87040
__global__ __launch_bounds__(256, 2) void score_hmma(
    const __nv_bfloat16* __restrict__ Hh, const __nv_bfloat16* __restrict__ Hl,
    float* __restrict__ S) {
    extern __shared__ char smem[];
    const int tid = threadIdx.x;
    const int warp = tid >> 5, lane = tid & 31;
    const int b = blockIdx.y, nt0 = blockIdx.x * 128, l = blockIdx.z;
    const size_t zq = (size_t)l * NALL * DDF + (size_t)NDN * DDF;
    const size_t zd = (size_t)l * NALL * DDF;
    float* Sl = S + (size_t)l * ATTS;
    __nv_bfloat16* sAh = (__nv_bfloat16*)(smem + SC_AH);
    __nv_bfloat16* sAl = (__nv_bfloat16*)(smem + SC_AL);
    __nv_bfloat16* sBh = (__nv_bfloat16*)(smem + SC_BH);
    __nv_bfloat16* sBl = (__nv_bfloat16*)(smem + SC_BL);

    for (int i = tid; i < 512; i += 256) {
        int row = i >> 4, c8 = (i & 15) << 3;
        size_t g = zq + ((size_t)b * 32 + row) * 128 + c8;
        *(uint4*)(sAh + row * 136 + c8) = *(const uint4*)(Hh + g);
        *(uint4*)(sAl + row * 136 + c8) = *(const uint4*)(Hl + g);
    }
    for (int i = tid; i < 2048; i += 256) {
        int row = i >> 4, c8 = (i & 15) << 3;
        size_t g = zd + ((size_t)b * 512 + nt0 + row) * 128 + c8;
        *(uint4*)(sBh + row * 136 + c8) = *(const uint4*)(Hh + g);
        *(uint4*)(sBl + row * 136 + c8) = *(const uint4*)(Hl + g);
    }
    __syncthreads();

    uint32_t sa_h = smem_u32(sAh) + (((lane & 15)) * 136 + ((lane & 16) ? 8 : 0)) * 2;
    uint32_t sa_l = sa_h + (SC_AL - SC_AH);
    uint32_t sb_h = smem_u32(sBh) + ((warp * 16 + (lane & 7)) * 136 + ((lane & 8) ? 8 : 0)) * 2;
    uint32_t sb_l = sb_h + (SC_BL - SC_BH);

    float acc[2][2][4];
#pragma unroll
    for (int mt = 0; mt < 2; mt++)
#pragma unroll
        for (int ch = 0; ch < 2; ch++)
#pragma unroll
            for (int j = 0; j < 4; j++) acc[mt][ch][j] = 0.f;

#pragma unroll
    for (int s = 0; s < 8; s++) {
        uint32_t RAh[2][4], RAl[2][4];
        LDSM_X4(RAh[0], sa_h + s * 32);
        LDSM_X4(RAh[1], sa_h + 4352 + s * 32);
        LDSM_X4(RAl[0], sa_l + s * 32);
        LDSM_X4(RAl[1], sa_l + 4352 + s * 32);
#pragma unroll
        for (int ch = 0; ch < 2; ch++) {
            uint32_t RBh[2], RBl[2];
            LDSM_X2(RBh, sb_h + ch * 2176 + s * 32);
            LDSM_X2(RBl, sb_l + ch * 2176 + s * 32);
#pragma unroll
            for (int mt = 0; mt < 2; mt++) {
                MMA16816(acc[mt][ch], RAh[mt], RBh);
                MMA16816(acc[mt][ch], RAh[mt], RBl);
                MMA16816(acc[mt][ch], RAl[mt], RBh);
            }
        }
    }
    const int g = lane >> 2, t2 = lane & 3;
#pragma unroll
    for (int mt = 0; mt < 2; mt++)
#pragma unroll
        for (int ch = 0; ch < 2; ch++) {
            int r = mt * 16 + g;
            int n = nt0 + warp * 16 + ch * 8 + t2 * 2;
            *(float2*)(Sl + ((size_t)b * 32 + r) * 512 + n) =
                make_float2(acc[mt][ch][0], acc[mt][ch][1]);
            *(float2*)(Sl + ((size_t)b * 32 + r + 8) * 512 + n) =
                make_float2(acc[mt][ch][2], acc[mt][ch][3]);
        }
}

// ====== fused NTN level kernel, z = l*64 + b; A-tile reused over 4 n-tiles ===
#define OFF_AH 0
#define OFF_AL 34816
#define OFF_BH 69632
#define OFF_BL 87040
#define OFF_LD 104448
#define OFF_LQ 108544
#define OFF_WK 109056
#define OFF_BN 109184
#define NTN_SMEM 109248

__global__ __launch_bounds__(256, 2) void ntn_fused_kern(
    const __nv_bfloat16* __restrict__ Ah3, const __nv_bfloat16* __restrict__ Al3,
    const __nv_bfloat16* __restrict__ Bh3, const __nv_bfloat16* __restrict__ Bl3,
    const float* __restrict__ lq3, const float* __restrict__ ld3,
    const float* __restrict__ bn1, const float* __restrict__ bn2,
    const float* __restrict__ bn3, const float* __restrict__ att3,
    const float* __restrict__ wk,
    float* __restrict__ e1, float* __restrict__ acc2, float* __restrict__ e3,
    float* __restrict__ accB) {
    extern __shared__ char smem[];
    const int tid = threadIdx.x;
    const int warp = tid >> 5, lane = tid & 31;
    const int z = blockIdx.z, l = z >> 6, b = z & 63;
    const int mt = blockIdx.y;
    const int hasB = (l == 2);
    const __nv_bfloat16* Ah = Ah3 + (size_t)l * QWS;
    const __nv_bfloat16* Al = Al3 + (size_t)l * QWS;
    const __nv_bfloat16* Bh = Bh3 + (size_t)l * NALL * DDF;
    const __nv_bfloat16* Bl = Bl3 + (size_t)l * NALL * DDF;
    const float* lq = lq3 + (size_t)l * NQN * KKN;
    const float* ld = ld3 + (size_t)l * NDN * KKN;
    const float* bn = (l == 0) ? bn1 : (l == 1) ? bn2 : bn3;
    const float* att = att3 + (size_t)l * ATTS;
    float* outA = (l == 0) ? e1 : (l == 1) ? acc2 : e3;
    const int wkofs = l * 32;

    __nv_bfloat16* sAh = (__nv_bfloat16*)(smem + OFF_AH);
    __nv_bfloat16* sAl = (__nv_bfloat16*)(smem + OFF_AL);
    __nv_bfloat16* sBh = (__nv_bfloat16*)(smem + OFF_BH);
    __nv_bfloat16* sBl = (__nv_bfloat16*)(smem + OFF_BL);
    float* s_ld = (float*)(smem + OFF_LD);
    float* s_lq = (float*)(smem + OFF_LQ);
    float* s_wk = (float*)(smem + OFF_WK);
    float* s_bn = (float*)(smem + OFF_BN);

    for (int i = tid; i < 2048; i += 256) {
        int row = i >> 4, c8 = (i & 15) << 3;
        size_t g = ((size_t)b * 512 + (size_t)mt * 128 + row) * 128 + c8;
        *(uint4*)(sAh + row * 136 + c8) = *(const uint4*)(Ah + g);
        *(uint4*)(sAl + row * 136 + c8) = *(const uint4*)(Al + g);
    }
    if (tid < 128) s_lq[tid] = lq[((size_t)b * 32 + mt * 8) * 16 + tid];
    if (tid < 32) s_wk[tid] = wk[wkofs + tid];
    if (tid < 16) s_bn[tid] = bn[tid];

    const int m0 = warp * 16;
    uint32_t sa_h = smem_u32(sAh) + ((m0 + (lane & 15)) * 136 + ((lane & 16) ? 8 : 0)) * 2;
    uint32_t sa_l = sa_h + (OFF_BH - OFF_AL);
    uint32_t sb_h = smem_u32(sBh) + ((lane & 7) * 136 + ((lane & 8) ? 8 : 0)) * 2;
    uint32_t sb_l = sb_h + (OFF_LD - OFF_BL);

    const int q = mt * 8 + warp;
    const int k0 = lane >> 2;
    const int c2 = (lane & 3) * 2;

#pragma unroll 1
    for (int it = 0; it < 4; it++) {
        const int nt = blockIdx.x * 4 + it;
        if (it > 0) __syncthreads();
        for (int i = tid; i < 1024; i += 256) {
            int row = i >> 4, c8 = (i & 15) << 3;
            size_t g = ((size_t)b * 512 + (size_t)nt * 64 + row) * 128 + c8;
            *(uint4*)(sBh + row * 136 + c8) = *(const uint4*)(Bh + g);
            *(uint4*)(sBl + row * 136 + c8) = *(const uint4*)(Bl + g);
        }
        for (int i = tid; i < 256; i += 256)
            ((float4*)s_ld)[i] = ((const float4*)(ld + ((size_t)b * 512 + (size_t)nt * 64) * 16))[i];
        __syncthreads();

        float acc[8][4];
#pragma unroll
        for (int c = 0; c < 8; c++)
#pragma unroll
            for (int j = 0; j < 4; j++) acc[c][j] = 0.f;

#pragma unroll
        for (int s = 0; s < 8; s++) {
            uint32_t RAh[4], RAl[4];
            LDSM_X4(RAh, sa_h + s * 32);
            LDSM_X4(RAl, sa_l + s * 32);
#pragma unroll
            for (int ch = 0; ch < 8; ch++) {
                uint32_t RBh[2], RBl[2];
                LDSM_X2(RBh, sb_h + ch * 2176 + s * 32);
                LDSM_X2(RBl, sb_l + ch * 2176 + s * 32);
                MMA16816(acc[ch], RAh, RBh);
                MMA16816(acc[ch], RAh, RBl);
                MMA16816(acc[ch], RAl, RBh);
            }
        }

        const float lq0 = s_lq[warp * 16 + k0] + s_bn[k0];
        const float lq1 = s_lq[warp * 16 + k0 + 8] + s_bn[k0 + 8];
        const float al0 = s_wk[k0], al1 = s_wk[k0 + 8];
        const float be0 = s_wk[16 + k0], be1 = s_wk[16 + k0 + 8];

#pragma unroll
        for (int ch = 0; ch < 8; ch++) {
            int n0 = ch * 8 + c2;
            float sg00 = 1.f / (1.f + __expf(-(acc[ch][0] + lq0 + s_ld[n0 * 16 + k0])));
            float sg01 = 1.f / (1.f + __expf(-(acc[ch][1] + lq0 + s_ld[(n0 + 1) * 16 + k0])));
            float sg10 = 1.f / (1.f + __expf(-(acc[ch][2] + lq1 + s_ld[n0 * 16 + k0 + 8])));
            float sg11 = 1.f / (1.f + __expf(-(acc[ch][3] + lq1 + s_ld[(n0 + 1) * 16 + k0 + 8])));
            float u0 = al0 * sg00 + al1 * sg10;
            float u1 = al0 * sg01 + al1 * sg11;
#pragma unroll
            for (int off = 4; off < 32; off <<= 1) {
                u0 += __shfl_xor_sync(0xffffffffu, u0, off);
                u1 += __shfl_xor_sync(0xffffffffu, u1, off);
            }
            float v0 = 0.f, v1 = 0.f;
            if (hasB) {
                v0 = be0 * sg00 + be1 * sg10;
                v1 = be0 * sg01 + be1 * sg11;
#pragma unroll
                for (int off = 4; off < 32; off <<= 1) {
                    v0 += __shfl_xor_sync(0xffffffffu, v0, off);
                    v1 += __shfl_xor_sync(0xffffffffu, v1, off);
                }
            }
            if (lane < 4) {
                size_t o = ((size_t)b * 32 + q) * 512 + (size_t)nt * 64 + ch * 8 + lane * 2;
                float a0 = att[o], a1 = att[o + 1];
                outA[o]     = u0 * a0;
                outA[o + 1] = u1 * a1;
                if (hasB) {
                    accB[o]     = v0 * a0;
                    accB[o + 1] = v1 * a1;
                }
            }
        }
    }
}

// ----------------------------- softmaxes -------------------------------------
__device__ __forceinline__ float warp_max(float v) {
#pragma unroll
    for (int o = 16; o > 0; o >>= 1) v = fmaxf(v, __shfl_xor_sync(0xffffffffu, v, o));
    return v;
}
__device__ __forceinline__ float warp_sum(float v) {
#pragma unroll
    for (int o = 16; o > 0; o >>= 1) v += __shfl_xor_sync(0xffffffffu, v, o);
    return v;
}
__device__ __forceinline__ void softmax16(float* v) {
    float m = -1e30f;
#pragma unroll
    for (int i = 0; i < 16; i++) m = fmaxf(m, v[i]);
    m = warp_max(m);
    float s = 0.f;
#pragma unroll
    for (int i = 0; i < 16; i++) { v[i] = __expf(v[i] - m); s += v[i]; }
    s = warp_sum(s);
    float inv = 1.f / s;
#pragma unroll
    for (int i = 0; i < 16; i++) v[i] *= inv;
}

__global__ void row_softmax512(float* __restrict__ p, float scale) {
    int row = blockIdx.x * 8 + (threadIdx.x >> 5);
    int lane = threadIdx.x & 31;
    float* r = p + (size_t)row * 512 + lane * 16;
    float v[16];
#pragma unroll
    for (int j = 0; j < 4; j++) {
        float4 t = *(float4*)(r + j * 4);
        v[j*4+0]=t.x*scale; v[j*4+1]=t.y*scale; v[j*4+2]=t.z*scale; v[j*4+3]=t.w*scale;
    }
    softmax16(v);
#pragma unroll
    for (int j = 0; j < 4; j++)
        *(float4*)(r + j * 4) = make_float4(v[j*4+0], v[j*4+1], v[j*4+2], v[j*4+3]);
}

__global__ void final_fused(const float* __restrict__ e1, const float* __restrict__ acc,
                            const float* __restrict__ accB, const float* __restrict__ e3,
                            const float* __restrict__ wk, float* __restrict__ out) {
    float w0 = wk[96], w2 = wk[97];
    int row = blockIdx.x * 8 + (threadIdx.x >> 5);
    int lane = threadIdx.x & 31;
    size_t base = (size_t)row * 512 + lane * 16;
    float a[16], c[16], v[16];
#pragma unroll
    for (int j = 0; j < 4; j++) {
        float4 t = *(const float4*)(e1 + base + j * 4);
        a[j*4+0]=t.x; a[j*4+1]=t.y; a[j*4+2]=t.z; a[j*4+3]=t.w;
        float4 u = *(const float4*)(e3 + base + j * 4);
        c[j*4+0]=u.x; c[j*4+1]=u.y; c[j*4+2]=u.z; c[j*4+3]=u.w;
    }
    softmax16(a);
    softmax16(c);
#pragma unroll
    for (int j = 0; j < 4; j++) {
        float4 b = *(const float4*)(acc + base + j * 4);
        float4 bb = *(const float4*)(accB + base + j * 4);
        v[j*4+0] = w0*a[j*4+0] + b.x + bb.x + w2*c[j*4+0];
        v[j*4+1] = w0*a[j*4+1] + b.y + bb.y + w2*c[j*4+1];
        v[j*4+2] = w0*a[j*4+2] + b.z + bb.z + w2*c[j*4+2];
        v[j*4+3] = w0*a[j*4+3] + b.w + bb.w + w2*c[j*4+3];
    }
    softmax16(v);
#pragma unroll
    for (int j = 0; j < 4; j++)
        *(float4*)(out + base + j * 4) = make_float4(v[j*4+0], v[j*4+1], v[j*4+2], v[j*4+3]);
}

// ------------------------------- host side -----------------------------------
static inline void* symaddr(const void* sym) {
    void* p = nullptr;
    cudaGetSymbolAddress(&p, sym);
    return p;
}

extern "C" void kernel_launch(void* const* d_in, const int* in_sizes, int n_in,
                              void* d_out, int out_size) {
    const float *x_d, *x_q;
    const int *ei_d, *ei_q;
    if (in_sizes[1] == 2 * EDM) {
        x_d = (const float*)d_in[0]; ei_d = (const int*)d_in[1];
        x_q = (const float*)d_in[2]; ei_q = (const int*)d_in[3];
    } else {
        x_d = (const float*)d_in[0]; x_q = (const float*)d_in[1];
        ei_d = (const int*)d_in[2]; ei_q = (const int*)d_in[3];
    }
    const float* W1 = (const float*)d_in[6];  const float* b1 = (const float*)d_in[7];
    const float* W2 = (const float*)d_in[8];  const float* b2 = (const float*)d_in[9];
    const float* W3 = (const float*)d_in[10]; const float* b3 = (const float*)d_in[11];
    const float* Wn[3] = {(const float*)d_in[12], (const float*)d_in[17], (const float*)d_in[22]};
    const float* Vn[3] = {(const float*)d_in[13], (const float*)d_in[18], (const float*)d_in[23]};
    const float* bn[3] = {(const float*)d_in[14], (const float*)d_in[19], (const float*)d_in[24]};
    const float* cw1 = (const float*)d_in[15];
    const float* cw2 = (const float*)d_in[20];
    const float* cw3 = (const float*)d_in[25];
    const float* w_end = (const float*)d_in[27];

    cudaFuncSetAttribute(hmma_gemm<0>, cudaFuncAttributeMaxDynamicSharedMemorySize, HG_SMEM);
    cudaFuncSetAttribute(hmma_gemm<1>, cudaFuncAttributeMaxDynamicSharedMemorySize, HG_SMEM);
    cudaFuncSetAttribute(score_hmma,   cudaFuncAttributeMaxDynamicSharedMemorySize, SC_SMEM);
    cudaFuncSetAttribute(ntn_fused_kern, cudaFuncAttributeMaxDynamicSharedMemorySize, NTN_SMEM);

    int* p_indeg = (int*)symaddr(g_indeg);   int* p_fill = (int*)symaddr(g_fill);
    int* p_rows = (int*)symaddr(g_rows);     float* p_dinv = (float*)symaddr(g_dinv);
    int* p_cols = (int*)symaddr(g_cols);     float* p_vals = (float*)symaddr(g_vals);
    float* p_xw = (float*)symaddr(g_xw);
    float* p_att3 = (float*)symaddr(g_att3);
    float* p_lq3 = (float*)symaddr(g_lq3);   float* p_ld3 = (float*)symaddr(g_ld3);
    float* p_e1 = (float*)symaddr(g_e1);     float* p_e3 = (float*)symaddr(g_e3);
    float* p_acc = (float*)symaddr(g_acc);   float* p_accB = (float*)symaddr(g_accB);
    float* p_wk = (float*)symaddr(g_wk);
    __nv_bfloat16* p_hallh = (__nv_bfloat16*)symaddr(g_hallh);
    __nv_bfloat16* p_halll = (__nv_bfloat16*)symaddr(g_halll);
    __nv_bfloat16* p_qwh3 = (__nv_bfloat16*)symaddr(g_qwh3);
    __nv_bfloat16* p_qwl3 = (__nv_bfloat16*)symaddr(g_qwl3);
    __nv_bfloat16* p_xh = (__nv_bfloat16*)symaddr(g_xh);
    __nv_bfloat16* p_xl = (__nv_bfloat16*)symaddr(g_xl);
    __nv_bfloat16* p_w1th = (__nv_bfloat16*)symaddr(g_w1th);
    __nv_bfloat16* p_w1tl = (__nv_bfloat16*)symaddr(g_w1tl);
    __nv_bfloat16* p_w2th = (__nv_bfloat16*)symaddr(g_w2th);
    __nv_bfloat16* p_w2tl = (__nv_bfloat16*)symaddr(g_w2tl);
    __nv_bfloat16* p_w3th = (__nv_bfloat16*)symaddr(g_w3th);
    __nv_bfloat16* p_w3tl = (__nv_bfloat16*)symaddr(g_w3tl);
    __nv_bfloat16* p_wnth = (__nv_bfloat16*)symaddr(g_wnth);
    __nv_bfloat16* p_wntl = (__nv_bfloat16*)symaddr(g_wntl);
    float* out = (float*)d_out;

    const int* src_d = ei_d;           const int* dst_d = ei_d + EDM;
    const int* src_q = ei_q;           const int* dst_q = ei_q + EQM;
    const __nv_bfloat16* w_h[3] = {p_w1th, p_w2th, p_w3th};
    const __nv_bfloat16* w_l[3] = {p_w1tl, p_w2tl, p_w3tl};
    const float* bias[3] = {b1, b2, b3};

    prep_all<<<9841, 256>>>(W1, W2, W3, Wn[0], Wn[1], Wn[2], x_d, x_q,
                            cw1, cw2, cw3, w_end,
                            p_w1th, p_w1tl, p_w2th, p_w2tl, p_w3th, p_w3tl,
                            p_wnth, p_wntl, p_xh, p_xl, p_wk, p_indeg, p_fill);
    count_all_kern<<<(EALL + 255) / 256, 256>>>(dst_d, dst_q, p_indeg);
    scan_dinv_kern<<<128, 512>>>(p_indeg, p_rows, p_dinv);
    fill_all_kern<<<(EALL + 255) / 256, 256>>>(src_d, dst_d, src_q, dst_q,
                                               p_dinv, p_rows, p_fill, p_cols, p_vals);
    for (int l = 0; l < 3; l++) {
        const __nv_bfloat16* Ah = (l == 0) ? p_xh : p_hallh + (size_t)(l - 1) * NALL * DDF;
        const __nv_bfloat16* Al = (l == 0) ? p_xl : p_halll + (size_t)(l - 1) * NALL * DDF;
        hmma_gemm<0><<<dim3(1, NALL / 128, 1), 256, HG_SMEM>>>(
            Ah, Al, w_h[l], w_l[l], p_xw, nullptr, nullptr, 128, 0, 0, 0);
        spmm_gcn<<<NALL * 32 / 256, 256>>>(p_xw, p_rows, p_cols, p_vals, p_indeg, p_dinv,
                                           bias[l],
                                           p_hallh + (size_t)l * NALL * DDF,
                                           p_halll + (size_t)l * NALL * DDF,
                                           Vn[l],
                                           p_lq3 + (size_t)l * NQN * KKN,
                                           p_ld3 + (size_t)l * NDN * KKN, NALL);
    }
    score_hmma<<<dim3(4, BBATCH, 3), 256, SC_SMEM>>>(p_hallh, p_halll, p_att3);
    row_softmax512<<<768, 256>>>(p_att3, 0.08838834764831845f);
    hmma_gemm<1><<<dim3(16, 16, 3), 256, HG_SMEM>>>(
        p_hallh + (size_t)NDN * DDF, p_halll + (size_t)NDN * DDF, p_wnth, p_wntl,
        nullptr, p_qwh3, p_qwl3, 0, (long)NALL * DDF, 2048L * 128, (long)QWS);
    ntn_fused_kern<<<dim3(2, 4, 192), 256, NTN_SMEM>>>(
        p_qwh3, p_qwl3, p_hallh, p_halll, p_lq3, p_ld3,
        bn[0], bn[1], bn[2], p_att3, p_wk, p_e1, p_acc, p_e3, p_accB);
    final_fused<<<256, 256>>>(p_e1, p_acc, p_accB, p_e3, p_wk, out);
}

// round 14
// speedup vs baseline: 1.0017x; 1.0017x over previous
#include <cuda_runtime.h>
#include <cuda_bf16.h>
#include <math.h>
#include <stdint.h>

#define BBATCH 64
#define NQD    32
#define NDD    512
#define DINF   64
#define DDF    128
#define KKN    16
#define NDN    (BBATCH*NDD)      // 32768
#define NQN    (BBATCH*NQD)      // 2048
#define NALL   (NDN+NQN)         // 34816
#define EDM    (NDN*8)           // 262144
#define EQM    (NQN*8)           // 16384
#define EALL   (EDM+EQM)         // 278528
#define ATTS   ((size_t)BBATCH*NQD*NDD)
#define QWS    ((size_t)BBATCH*512*DDF)

// ------------------------- static device scratch ----------------------------
__device__ float g_dinv[NALL];
__device__ int   g_indeg[NALL];
__device__ int   g_rows[NALL];
__device__ int   g_cols[EALL];
__device__ float g_vals[EALL];
__device__ float g_xw[(size_t)NALL*DDF];
__device__ float g_att3[3*ATTS];
__device__ float g_lq3[3*NQN*KKN];
__device__ float g_ld3[3*NDN*KKN];
__device__ float g_e1[ATTS];
__device__ float g_e3[ATTS];
__device__ float g_acc[ATTS];
__device__ float g_accB[ATTS];
__device__ float g_wk[128];
__device__ __nv_bfloat16 g_hallh[(size_t)3*NALL*DDF];
__device__ __nv_bfloat16 g_halll[(size_t)3*NALL*DDF];
__device__ __nv_bfloat16 g_qwh3[3*QWS];
__device__ __nv_bfloat16 g_qwl3[3*QWS];
__device__ __nv_bfloat16 g_xh[(size_t)NALL*DDF], g_xl[(size_t)NALL*DDF];
__device__ __nv_bfloat16 g_w1th[DDF*DDF], g_w1tl[DDF*DDF];
__device__ __nv_bfloat16 g_w2th[DDF*DDF], g_w2tl[DDF*DDF];
__device__ __nv_bfloat16 g_w3th[DDF*DDF], g_w3tl[DDF*DDF];
__device__ __nv_bfloat16 g_wnth[(size_t)3*KKN*DDF*DDF], g_wntl[(size_t)3*KKN*DDF*DDF];

// --------------------------- PTX helpers -------------------------------------
__device__ __forceinline__ uint32_t smem_u32(const void* p) {
    uint32_t a;
    asm("{ .reg .u64 t; cvta.to.shared.u64 t, %1; cvt.u32.u64 %0, t; }" : "=r"(a) : "l"(p));
    return a;
}
#define LDSM_X4(r, a) \
    asm volatile("ldmatrix.sync.aligned.m8n8.x4.shared.b16 {%0,%1,%2,%3}, [%4];" \
        : "=r"((r)[0]), "=r"((r)[1]), "=r"((r)[2]), "=r"((r)[3]) : "r"(a))
#define LDSM_X2(r, a) \
    asm volatile("ldmatrix.sync.aligned.m8n8.x2.shared.b16 {%0,%1}, [%2];" \
        : "=r"((r)[0]), "=r"((r)[1]) : "r"(a))
#define MMA16816(d, a, b) \
    asm volatile("mma.sync.aligned.m16n8k16.row.col.f32.bf16.bf16.f32 " \
        "{%0,%1,%2,%3},{%4,%5,%6,%7},{%8,%9},{%0,%1,%2,%3};" \
        : "+f"((d)[0]), "+f"((d)[1]), "+f"((d)[2]), "+f"((d)[3]) \
        : "r"((a)[0]), "r"((a)[1]), "r"((a)[2]), "r"((a)[3]), "r"((b)[0]), "r"((b)[1]))

// =================== fused prep: weights + inputs + wk =======================
__global__ void prep_all(
    const float* __restrict__ W1, const float* __restrict__ W2, const float* __restrict__ W3,
    const float* __restrict__ Wn1, const float* __restrict__ Wn2, const float* __restrict__ Wn3,
    const float* __restrict__ x_d, const float* __restrict__ x_q,
    const float* __restrict__ cw1, const float* __restrict__ cw2, const float* __restrict__ cw3,
    const float* __restrict__ w_end,
    __nv_bfloat16* __restrict__ w1th, __nv_bfloat16* __restrict__ w1tl,
    __nv_bfloat16* __restrict__ w2th, __nv_bfloat16* __restrict__ w2tl,
    __nv_bfloat16* __restrict__ w3th, __nv_bfloat16* __restrict__ w3tl,
    __nv_bfloat16* __restrict__ wnth, __nv_bfloat16* __restrict__ wntl,
    __nv_bfloat16* __restrict__ xh, __nv_bfloat16* __restrict__ xl,
    float* __restrict__ wk) {
    __shared__ float ts[32][33];
    const int blk = blockIdx.x, tid = threadIdx.x;
    if (blk < 800) {
        const float* src; __nv_bfloat16 *oh, *ol; int k, t2;
        if (blk < 16)      { src = W2; oh = w2th; ol = w2tl; k = 0; t2 = blk; }
        else if (blk < 32) { src = W3; oh = w3th; ol = w3tl; k = 0; t2 = blk - 16; }
        else {
            int t = blk - 32, l = t >> 8, rem = t & 255;
            k = rem >> 4; t2 = rem & 15;
            src = (l == 0) ? Wn1 : (l == 1) ? Wn2 : Wn3;
            oh = wnth + (size_t)l * 2048 * 128; ol = wntl + (size_t)l * 2048 * 128;
        }
        int e0 = (t2 & 3) * 32, d0 = (t2 >> 2) * 32;
        int tx = tid & 31, ty = tid >> 5;
        const float* ink = src + (size_t)k * 16384;
#pragma unroll
        for (int j = 0; j < 32; j += 8)
            ts[ty + j][tx] = ink[(size_t)(d0 + ty + j) * 128 + e0 + tx];
        __syncthreads();
#pragma unroll
        for (int j = 0; j < 32; j += 8) {
            float v = ts[tx][ty + j];
            size_t o = ((size_t)k * 128 + e0 + ty + j) * 128 + d0 + tx;
            __nv_bfloat16 h = __float2bfloat16(v);
            oh[o] = h;
            ol[o] = __float2bfloat16(v - __bfloat162float(h));
        }
    } else if (blk < 864) {
        int i = (blk - 800) * 256 + tid;
        int e = i >> 7, d = i & 127;
        float v = (d < 64) ? W1[d * 128 + e] : 0.f;
        __nv_bfloat16 h = __float2bfloat16(v);
        w1th[i] = h;
        w1tl[i] = __float2bfloat16(v - __bfloat162float(h));
    } else if (blk < 864 + 8192) {
        int i = (blk - 864) * 256 + tid;
        int node = i >> 6, c = i & 63;
        float v = x_d[i];
        __nv_bfloat16 h = __float2bfloat16(v);
        size_t o = (size_t)node * 128 + c;
        xh[o] = h; xl[o] = __float2bfloat16(v - __bfloat162float(h));
        xh[o + 64] = __float2bfloat16(0.f);
        xl[o + 64] = __float2bfloat16(0.f);
    } else if (blk < 864 + 8192 + 512) {
        int i = (blk - 864 - 8192) * 256 + tid;
        int node = NDN + (i >> 6), c = i & 63;
        float v = x_q[i];
        __nv_bfloat16 h = __float2bfloat16(v);
        size_t o = (size_t)node * 128 + c;
        xh[o] = h; xl[o] = __float2bfloat16(v - __bfloat162float(h));
        xh[o + 64] = __float2bfloat16(0.f);
        xl[o + 64] = __float2bfloat16(0.f);
    } else {
        int k = tid;
        if (k < 16) {
            wk[k]      = cw1[k];                              wk[16 + k] = 0.f;
            wk[32 + k] = w_end[1] * cw2[k] + w_end[19 + k];   wk[48 + k] = 0.f;
            wk[64 + k] = cw3[k];
            wk[80 + k] = w_end[3 + k] + w_end[35 + k];
        }
        if (k == 0) { wk[96] = w_end[0]; wk[97] = w_end[2]; }
    }
}

// ========== CSR build: one CTA per graph, all atomics in shared mem ==========
__global__ __launch_bounds__(512) void csr_build_kern(
    const int* __restrict__ src_d, const int* __restrict__ dst_d,
    const int* __restrict__ src_q, const int* __restrict__ dst_q,
    int* __restrict__ indeg, int* __restrict__ rows, float* __restrict__ dinv,
    int* __restrict__ cols, float* __restrict__ vals) {
    __shared__ int sdeg[512];
    __shared__ int sfill[512];
    __shared__ int srow[512];
    __shared__ float sdinv[512];
    const int g = blockIdx.x, t = threadIdx.x;
    int nper, eper, nodebase, lbase, ebase, gEdgeBase, goff;
    const int *src, *dst;
    if (g < 64) {
        nper = 512; eper = 4096; nodebase = g * 512; lbase = g * 512;
        ebase = g * 4096; gEdgeBase = g * 4096; goff = 0;
        src = src_d; dst = dst_d;
    } else {
        int gq = g - 64;
        nper = 32; eper = 256; nodebase = NDN + gq * 32; lbase = gq * 32;
        ebase = gq * 256; gEdgeBase = EDM + gq * 256; goff = NDN;
        src = src_q; dst = dst_q;
    }
    if (t < nper) { sdeg[t] = 0; sfill[t] = 0; }
    __syncthreads();
    for (int e = t; e < eper; e += 512)
        atomicAdd(&sdeg[dst[ebase + e] - lbase], 1);
    __syncthreads();
    int v = (t < nper) ? sdeg[t] : 0;
    srow[t] = v;
    __syncthreads();
    for (int off = 1; off < 512; off <<= 1) {
        int x = (t >= off) ? srow[t - off] : 0;
        __syncthreads();
        srow[t] += x;
        __syncthreads();
    }
    if (t < nper) {
        int excl = srow[t] - v;
        srow[t] = excl;
        float di = rsqrtf((float)v + 1.0f);
        sdinv[t] = di;
        indeg[nodebase + t] = v;
        rows[nodebase + t] = gEdgeBase + excl;
        dinv[nodebase + t] = di;
    }
    __syncthreads();
    for (int e = t; e < eper; e += 512) {
        int s = src[ebase + e] - lbase, d2 = dst[ebase + e] - lbase;
        int p = atomicAdd(&sfill[d2], 1);
        int idx = gEdgeBase + srow[d2] + p;
        cols[idx] = s + lbase + goff;
        vals[idx] = sdinv[s] * sdinv[d2];
    }
}

// ------ GCN aggregation: lane-parallel index prefetch + 4-way batched gather -
__global__ void spmm_gcn(const float* __restrict__ h, const int* __restrict__ rows,
                         const int* __restrict__ cols, const float* __restrict__ vals,
                         const int* __restrict__ indeg, const float* __restrict__ dinv,
                         const float* __restrict__ bias,
                         __nv_bfloat16* __restrict__ oh, __nv_bfloat16* __restrict__ ol,
                         const float* __restrict__ Vn,
                         float* __restrict__ lq, float* __restrict__ ld, int N) {
    const unsigned FULL = 0xffffffffu;
    int t = blockIdx.x * blockDim.x + threadIdx.x;
    int node = t >> 5, lane = t & 31;
    if (node >= N) return;
    float di = dinv[node];
    float self = di * di;
    float4 hv = *(const float4*)(h + (size_t)node * 128 + lane * 4);
    float ax = self * hv.x, ay = self * hv.y, az = self * hv.z, aw = self * hv.w;
    int r0 = rows[node], cnt = indeg[node];
    int cnt32 = cnt < 32 ? cnt : 32;
    int myc = 0; float myw = 0.f;
    if (lane < cnt32) { myc = __ldg(&cols[r0 + lane]); myw = __ldg(&vals[r0 + lane]); }
    int e = 0;
    for (; e + 4 <= cnt32; e += 4) {
        int sA = __shfl_sync(FULL, myc, e + 0); float wA = __shfl_sync(FULL, myw, e + 0);
        int sB = __shfl_sync(FULL, myc, e + 1); float wB = __shfl_sync(FULL, myw, e + 1);
        int sC = __shfl_sync(FULL, myc, e + 2); float wC = __shfl_sync(FULL, myw, e + 2);
        int sD = __shfl_sync(FULL, myc, e + 3); float wD = __shfl_sync(FULL, myw, e + 3);
        float4 a0 = *(const float4*)(h + (size_t)sA * 128 + lane * 4);
        float4 a1 = *(const float4*)(h + (size_t)sB * 128 + lane * 4);
        float4 a2 = *(const float4*)(h + (size_t)sC * 128 + lane * 4);
        float4 a3 = *(const float4*)(h + (size_t)sD * 128 + lane * 4);
        ax += wA * a0.x; ay += wA * a0.y; az += wA * a0.z; aw += wA * a0.w;
        ax += wB * a1.x; ay += wB * a1.y; az += wB * a1.z; aw += wB * a1.w;
        ax += wC * a2.x; ay += wC * a2.y; az += wC * a2.z; aw += wC * a2.w;
        ax += wD * a3.x; ay += wD * a3.y; az += wD * a3.z; aw += wD * a3.w;
    }
    for (; e < cnt32; e++) {
        int s = __shfl_sync(FULL, myc, e); float w = __shfl_sync(FULL, myw, e);
        float4 n4 = *(const float4*)(h + (size_t)s * 128 + lane * 4);
        ax += w * n4.x; ay += w * n4.y; az += w * n4.z; aw += w * n4.w;
    }
    for (; e < cnt; e++) {
        int s = __ldg(&cols[r0 + e]);
        float w = __ldg(&vals[r0 + e]);
        float4 n4 = *(const float4*)(h + (size_t)s * 128 + lane * 4);
        ax += w * n4.x; ay += w * n4.y; az += w * n4.z; aw += w * n4.w;
    }
    float4 b4 = *(const float4*)(bias + lane * 4);
    float4 o;
    o.x = fmaxf(ax + b4.x, 0.f); o.y = fmaxf(ay + b4.y, 0.f);
    o.z = fmaxf(az + b4.z, 0.f); o.w = fmaxf(aw + b4.w, 0.f);
    __nv_bfloat162 h01 = __floats2bfloat162_rn(o.x, o.y);
    __nv_bfloat162 h23 = __floats2bfloat162_rn(o.z, o.w);
    *(__nv_bfloat162*)(oh + (size_t)node * 128 + lane * 4)     = h01;
    *(__nv_bfloat162*)(oh + (size_t)node * 128 + lane * 4 + 2) = h23;
    *(__nv_bfloat162*)(ol + (size_t)node * 128 + lane * 4) =
        __floats2bfloat162_rn(o.x - __bfloat162float(h01.x), o.y - __bfloat162float(h01.y));
    *(__nv_bfloat162*)(ol + (size_t)node * 128 + lane * 4 + 2) =
        __floats2bfloat162_rn(o.z - __bfloat162float(h23.x), o.w - __bfloat162float(h23.y));

    const float* Vrow;
    float* outp;
    if (node < NDN) { Vrow = Vn + DDF; outp = ld + (size_t)node * 16; }
    else            { Vrow = Vn;       outp = lq + (size_t)(node - NDN) * 16; }
    float res = 0.f;
#pragma unroll
    for (int k = 0; k < 16; k++) {
        float4 v4 = __ldg((const float4*)(Vrow + k * 256 + lane * 4));
        float p = o.x * v4.x + o.y * v4.y + o.z * v4.z + o.w * v4.w;
#pragma unroll
        for (int off2 = 16; off2 > 0; off2 >>= 1)
            p += __shfl_xor_sync(FULL, p, off2);
        if (lane == k) res = p;
    }
    if (lane < 16) outp[lane] = res;
}

// ===================== generic split-bf16 HMMA GEMM ==========================
#define HG_AH 0
#define HG_AL 34816
#define HG_BH 69632
#define HG_BL 104448
#define HG_SMEM 139264

template<int EPI>
__global__ __launch_bounds__(256, 1) void hmma_gemm(
    const __nv_bfloat16* __restrict__ Ah, const __nv_bfloat16* __restrict__ Al,
    const __nv_bfloat16* __restrict__ Bh, const __nv_bfloat16* __restrict__ Bl,
    float* __restrict__ outF, __nv_bfloat16* __restrict__ oh,
    __nv_bfloat16* __restrict__ ol, int ldC,
    long zsA, long zsB, long zsO) {
    extern __shared__ char smem[];
    const int tid = threadIdx.x;
    const int warp = tid >> 5, lane = tid & 31;
    const int mt0 = blockIdx.y * 128, nt0 = blockIdx.x * 128;
    const long za = (long)blockIdx.z * zsA, zb = (long)blockIdx.z * zsB;
    const long zo = (long)blockIdx.z * zsO;
    __nv_bfloat16* sAh = (__nv_bfloat16*)(smem + HG_AH);
    __nv_bfloat16* sAl = (__nv_bfloat16*)(smem + HG_AL);
    __nv_bfloat16* sBh = (__nv_bfloat16*)(smem + HG_BH);
    __nv_bfloat16* sBl = (__nv_bfloat16*)(smem + HG_BL);

    for (int i = tid; i < 2048; i += 256) {
        int row = i >> 4, c8 = (i & 15) << 3;
        size_t g = za + ((size_t)(mt0 + row)) * 128 + c8;
        *(uint4*)(sAh + row * 136 + c8) = *(const uint4*)(Ah + g);
        *(uint4*)(sAl + row * 136 + c8) = *(const uint4*)(Al + g);
        size_t gb = zb + ((size_t)(nt0 + row)) * 128 + c8;
        *(uint4*)(sBh + row * 136 + c8) = *(const uint4*)(Bh + gb);
        *(uint4*)(sBl + row * 136 + c8) = *(const uint4*)(Bl + gb);
    }
    __syncthreads();

    const int wy = warp >> 1, wx = warp & 1;
    uint32_t sa_h = smem_u32(sAh) + ((wy * 32 + (lane & 15)) * 136 + ((lane & 16) ? 8 : 0)) * 2;
    uint32_t sa_l = sa_h + (HG_AL - HG_AH);
    uint32_t sb_h = smem_u32(sBh) + ((wx * 64 + (lane & 7)) * 136 + ((lane & 8) ? 8 : 0)) * 2;
    uint32_t sb_l = sb_h + (HG_BL - HG_BH);

    float acc[2][8][4];
#pragma unroll
    for (int mt = 0; mt < 2; mt++)
#pragma unroll
        for (int ch = 0; ch < 8; ch++)
#pragma unroll
            for (int j = 0; j < 4; j++) acc[mt][ch][j] = 0.f;

#pragma unroll
    for (int s = 0; s < 8; s++) {
        uint32_t RAh[2][4], RAl[2][4];
        LDSM_X4(RAh[0], sa_h + s * 32);
        LDSM_X4(RAh[1], sa_h + 4352 + s * 32);
        LDSM_X4(RAl[0], sa_l + s * 32);
        LDSM_X4(RAl[1], sa_l + 4352 + s * 32);
#pragma unroll
        for (int ch = 0; ch < 8; ch++) {
            uint32_t RBh[2], RBl[2];
            LDSM_X2(RBh, sb_h + ch * 2176 + s * 32);
            LDSM_X2(RBl, sb_l + ch * 2176 + s * 32);
#pragma unroll
            for (int mt = 0; mt < 2; mt++) {
                MMA16816(acc[mt][ch], RAh[mt], RBh);
                MMA16816(acc[mt][ch], RAh[mt], RBl);
                MMA16816(acc[mt][ch], RAl[mt], RBh);
            }
        }
    }

    const int g = lane >> 2, t2 = lane & 3;
#pragma unroll
    for (int mt = 0; mt < 2; mt++) {
#pragma unroll
        for (int ch = 0; ch < 8; ch++) {
            int r = mt0 + wy * 32 + mt * 16 + g;
            int c = nt0 + wx * 64 + ch * 8 + t2 * 2;
            if (EPI == 0) {
                *(float2*)(outF + (size_t)r * ldC + c) =
                    make_float2(acc[mt][ch][0], acc[mt][ch][1]);
                *(float2*)(outF + (size_t)(r + 8) * ldC + c) =
                    make_float2(acc[mt][ch][2], acc[mt][ch][3]);
            } else {
                int kk = c >> 7, e = c & 127;
#pragma unroll
                for (int half = 0; half < 2; half++) {
                    int rr = r + half * 8;
                    int bb = rr >> 5, q = rr & 31;
                    size_t orow = zo + ((size_t)bb * 512 + q * 16 + kk) * 128 + e;
                    float v0 = acc[mt][ch][half * 2], v1 = acc[mt][ch][half * 2 + 1];
                    __nv_bfloat162 ph = __floats2bfloat162_rn(v0, v1);
                    *(__nv_bfloat162*)(oh + orow) = ph;
                    *(__nv_bfloat162*)(ol + orow) = __floats2bfloat162_rn(
                        v0 - __bfloat162float(ph.x), v1 - __bfloat162float(ph.y));
                }
            }
        }
    }
}

// ----------- attention scores via HMMA (z = level) ---------------------------
#define SC_AH 0
#define SC_AL 8704
#define SC_BH 17408
#define SC_BL 52224
#define SC_SMEM 87040
__global__ __launch_bounds__(256, 2) void score_hmma(
    const __nv_bfloat16* __restrict__ Hh, const __nv_bfloat16* __restrict__ Hl,
    float* __restrict__ S) {
    extern __shared__ char smem[];
    const int tid = threadIdx.x;
    const int warp = tid >> 5, lane = tid & 31;
    const int b = blockIdx.y, nt0 = blockIdx.x * 128, l = blockIdx.z;
    const size_t zq = (size_t)l * NALL * DDF + (size_t)NDN * DDF;
    const size_t zd = (size_t)l * NALL * DDF;
    float* Sl = S + (size_t)l * ATTS;
    __nv_bfloat16* sAh = (__nv_bfloat16*)(smem + SC_AH);
    __nv_bfloat16* sAl = (__nv_bfloat16*)(smem + SC_AL);
    __nv_bfloat16* sBh = (__nv_bfloat16*)(smem + SC_BH);
    __nv_bfloat16* sBl = (__nv_bfloat16*)(smem + SC_BL);

    for (int i = tid; i < 512; i += 256) {
        int row = i >> 4, c8 = (i & 15) << 3;
        size_t g = zq + ((size_t)b * 32 + row) * 128 + c8;
        *(uint4*)(sAh + row * 136 + c8) = *(const uint4*)(Hh + g);
        *(uint4*)(sAl + row * 136 + c8) = *(const uint4*)(Hl + g);
    }
    for (int i = tid; i < 2048; i += 256) {
        int row = i >> 4, c8 = (i & 15) << 3;
        size_t g = zd + ((size_t)b * 512 + nt0 + row) * 128 + c8;
        *(uint4*)(sBh + row * 136 + c8) = *(const uint4*)(Hh + g);
        *(uint4*)(sBl + row * 136 + c8) = *(const uint4*)(Hl + g);
    }
    __syncthreads();

    uint32_t sa_h = smem_u32(sAh) + (((lane & 15)) * 136 + ((lane & 16) ? 8 : 0)) * 2;
    uint32_t sa_l = sa_h + (SC_AL - SC_AH);
    uint32_t sb_h = smem_u32(sBh) + ((warp * 16 + (lane & 7)) * 136 + ((lane & 8) ? 8 : 0)) * 2;
    uint32_t sb_l = sb_h + (SC_BL - SC_BH);

    float acc[2][2][4];
#pragma unroll
    for (int mt = 0; mt < 2; mt++)
#pragma unroll
        for (int ch = 0; ch < 2; ch++)
#pragma unroll
            for (int j = 0; j < 4; j++) acc[mt][ch][j] = 0.f;

#pragma unroll
    for (int s = 0; s < 8; s++) {
        uint32_t RAh[2][4], RAl[2][4];
        LDSM_X4(RAh[0], sa_h + s * 32);
        LDSM_X4(RAh[1], sa_h + 4352 + s * 32);
        LDSM_X4(RAl[0], sa_l + s * 32);
        LDSM_X4(RAl[1], sa_l + 4352 + s * 32);
#pragma unroll
        for (int ch = 0; ch < 2; ch++) {
            uint32_t RBh[2], RBl[2];
            LDSM_X2(RBh, sb_h + ch * 2176 + s * 32);
            LDSM_X2(RBl, sb_l + ch * 2176 + s * 32);
#pragma unroll
            for (int mt = 0; mt < 2; mt++) {
                MMA16816(acc[mt][ch], RAh[mt], RBh);
                MMA16816(acc[mt][ch], RAh[mt], RBl);
                MMA16816(acc[mt][ch], RAl[mt], RBh);
            }
        }
    }
    const int g = lane >> 2, t2 = lane & 3;
#pragma unroll
    for (int mt = 0; mt < 2; mt++)
#pragma unroll
        for (int ch = 0; ch < 2; ch++) {
            int r = mt * 16 + g;
            int n = nt0 + warp * 16 + ch * 8 + t2 * 2;
            *(float2*)(Sl + ((size_t)b * 32 + r) * 512 + n) =
                make_float2(acc[mt][ch][0], acc[mt][ch][1]);
            *(float2*)(Sl + ((size_t)b * 32 + r + 8) * 512 + n) =
                make_float2(acc[mt][ch][2], acc[mt][ch][3]);
        }
}

// ====== fused NTN level kernel, z = l*64 + b; A-tile reused over 4 n-tiles ===
#define OFF_AH 0
#define OFF_AL 34816
#define OFF_BH 69632
#define OFF_BL 87040
#define OFF_LD 104448
#define OFF_LQ 108544
#define OFF_WK 109056
#define OFF_BN 109184
#define NTN_SMEM 109248

__global__ __launch_bounds__(256, 2) void ntn_fused_kern(
    const __nv_bfloat16* __restrict__ Ah3, const __nv_bfloat16* __restrict__ Al3,
    const __nv_bfloat16* __restrict__ Bh3, const __nv_bfloat16* __restrict__ Bl3,
    const float* __restrict__ lq3, const float* __restrict__ ld3,
    const float* __restrict__ bn1, const float* __restrict__ bn2,
    const float* __restrict__ bn3, const float* __restrict__ att3,
    const float* __restrict__ wk,
    float* __restrict__ e1, float* __restrict__ acc2, float* __restrict__ e3,
    float* __restrict__ accB) {
    extern __shared__ char smem[];
    const int tid = threadIdx.x;
    const int warp = tid >> 5, lane = tid & 31;
    const int z = blockIdx.z, l = z >> 6, b = z & 63;
    const int mt = blockIdx.y;
    const int hasB = (l == 2);
    const __nv_bfloat16* Ah = Ah3 + (size_t)l * QWS;
    const __nv_bfloat16* Al = Al3 + (size_t)l * QWS;
    const __nv_bfloat16* Bh = Bh3 + (size_t)l * NALL * DDF;
    const __nv_bfloat16* Bl = Bl3 + (size_t)l * NALL * DDF;
    const float* lq = lq3 + (size_t)l * NQN * KKN;
    const float* ld = ld3 + (size_t)l * NDN * KKN;
    const float* bn = (l == 0) ? bn1 : (l == 1) ? bn2 : bn3;
    const float* att = att3 + (size_t)l * ATTS;
    float* outA = (l == 0) ? e1 : (l == 1) ? acc2 : e3;
    const int wkofs = l * 32;

    __nv_bfloat16* sAh = (__nv_bfloat16*)(smem + OFF_AH);
    __nv_bfloat16* sAl = (__nv_bfloat16*)(smem + OFF_AL);
    __nv_bfloat16* sBh = (__nv_bfloat16*)(smem + OFF_BH);
    __nv_bfloat16* sBl = (__nv_bfloat16*)(smem + OFF_BL);
    float* s_ld = (float*)(smem + OFF_LD);
    float* s_lq = (float*)(smem + OFF_LQ);
    float* s_wk = (float*)(smem + OFF_WK);
    float* s_bn = (float*)(smem + OFF_BN);

    for (int i = tid; i < 2048; i += 256) {
        int row = i >> 4, c8 = (i & 15) << 3;
        size_t g = ((size_t)b * 512 + (size_t)mt * 128 + row) * 128 + c8;
        *(uint4*)(sAh + row * 136 + c8) = *(const uint4*)(Ah + g);
        *(uint4*)(sAl + row * 136 + c8) = *(const uint4*)(Al + g);
    }
    if (tid < 128) s_lq[tid] = lq[((size_t)b * 32 + mt * 8) * 16 + tid];
    if (tid < 32) s_wk[tid] = wk[wkofs + tid];
    if (tid < 16) s_bn[tid] = bn[tid];

    const int m0 = warp * 16;
    uint32_t sa_h = smem_u32(sAh) + ((m0 + (lane & 15)) * 136 + ((lane & 16) ? 8 : 0)) * 2;
    uint32_t sa_l = sa_h + (OFF_BH - OFF_AL);
    uint32_t sb_h = smem_u32(sBh) + ((lane & 7) * 136 + ((lane & 8) ? 8 : 0)) * 2;
    uint32_t sb_l = sb_h + (OFF_LD - OFF_BL);

    const int q = mt * 8 + warp;
    const int k0 = lane >> 2;
    const int c2 = (lane & 3) * 2;

#pragma unroll 1
    for (int it = 0; it < 4; it++) {
        const int nt = blockIdx.x * 4 + it;
        if (it > 0) __syncthreads();
        for (int i = tid; i < 1024; i += 256) {
            int row = i >> 4, c8 = (i & 15) << 3;
            size_t g = ((size_t)b * 512 + (size_t)nt * 64 + row) * 128 + c8;
            *(uint4*)(sBh + row * 136 + c8) = *(const uint4*)(Bh + g);
            *(uint4*)(sBl + row * 136 + c8) = *(const uint4*)(Bl + g);
        }
        for (int i = tid; i < 256; i += 256)
            ((float4*)s_ld)[i] = ((const float4*)(ld + ((size_t)b * 512 + (size_t)nt * 64) * 16))[i];
        __syncthreads();

        float acc[8][4];
#pragma unroll
        for (int c = 0; c < 8; c++)
#pragma unroll
            for (int j = 0; j < 4; j++) acc[c][j] = 0.f;

#pragma unroll
        for (int s = 0; s < 8; s++) {
            uint32_t RAh[4], RAl[4];
            LDSM_X4(RAh, sa_h + s * 32);
            LDSM_X4(RAl, sa_l + s * 32);
#pragma unroll
            for (int ch = 0; ch < 8; ch++) {
                uint32_t RBh[2], RBl[2];
                LDSM_X2(RBh, sb_h + ch * 2176 + s * 32);
                LDSM_X2(RBl, sb_l + ch * 2176 + s * 32);
                MMA16816(acc[ch], RAh, RBh);
                MMA16816(acc[ch], RAh, RBl);
                MMA16816(acc[ch], RAl, RBh);
            }
        }

        const float lq0 = s_lq[warp * 16 + k0] + s_bn[k0];
        const float lq1 = s_lq[warp * 16 + k0 + 8] + s_bn[k0 + 8];
        const float al0 = s_wk[k0], al1 = s_wk[k0 + 8];
        const float be0 = s_wk[16 + k0], be1 = s_wk[16 + k0 + 8];

#pragma unroll
        for (int ch = 0; ch < 8; ch++) {
            int n0 = ch * 8 + c2;
            float sg00 = 1.f / (1.f + __expf(-(acc[ch][0] + lq0 + s_ld[n0 * 16 + k0])));
            float sg01 = 1.f / (1.f + __expf(-(acc[ch][1] + lq0 + s_ld[(n0 + 1) * 16 + k0])));
            float sg10 = 1.f / (1.f + __expf(-(acc[ch][2] + lq1 + s_ld[n0 * 16 + k0 + 8])));
            float sg11 = 1.f / (1.f + __expf(-(acc[ch][3] + lq1 + s_ld[(n0 + 1) * 16 + k0 + 8])));
            float u0 = al0 * sg00 + al1 * sg10;
            float u1 = al0 * sg01 + al1 * sg11;
#pragma unroll
            for (int off = 4; off < 32; off <<= 1) {
                u0 += __shfl_xor_sync(0xffffffffu, u0, off);
                u1 += __shfl_xor_sync(0xffffffffu, u1, off);
            }
            float v0 = 0.f, v1 = 0.f;
            if (hasB) {
                v0 = be0 * sg00 + be1 * sg10;
                v1 = be0 * sg01 + be1 * sg11;
#pragma unroll
                for (int off = 4; off < 32; off <<= 1) {
                    v0 += __shfl_xor_sync(0xffffffffu, v0, off);
                    v1 += __shfl_xor_sync(0xffffffffu, v1, off);
                }
            }
            if (lane < 4) {
                size_t o = ((size_t)b * 32 + q) * 512 + (size_t)nt * 64 + ch * 8 + lane * 2;
                float a0 = att[o], a1 = att[o + 1];
                outA[o]     = u0 * a0;
                outA[o + 1] = u1 * a1;
                if (hasB) {
                    accB[o]     = v0 * a0;
                    accB[o + 1] = v1 * a1;
                }
            }
        }
    }
}

// ----------------------------- softmaxes -------------------------------------
__device__ __forceinline__ float warp_max(float v) {
#pragma unroll
    for (int o = 16; o > 0; o >>= 1) v = fmaxf(v, __shfl_xor_sync(0xffffffffu, v, o));
    return v;
}
__device__ __forceinline__ float warp_sum(float v) {
#pragma unroll
    for (int o = 16; o > 0; o >>= 1) v += __shfl_xor_sync(0xffffffffu, v, o);
    return v;
}
__device__ __forceinline__ void softmax16(float* v) {
    float m = -1e30f;
#pragma unroll
    for (int i = 0; i < 16; i++) m = fmaxf(m, v[i]);
    m = warp_max(m);
    float s = 0.f;
#pragma unroll
    for (int i = 0; i < 16; i++) { v[i] = __expf(v[i] - m); s += v[i]; }
    s = warp_sum(s);
    float inv = 1.f / s;
#pragma unroll
    for (int i = 0; i < 16; i++) v[i] *= inv;
}

__global__ void row_softmax512(float* __restrict__ p, float scale) {
    int row = blockIdx.x * 8 + (threadIdx.x >> 5);
    int lane = threadIdx.x & 31;
    float* r = p + (size_t)row * 512 + lane * 16;
    float v[16];
#pragma unroll
    for (int j = 0; j < 4; j++) {
        float4 t = *(float4*)(r + j * 4);
        v[j*4+0]=t.x*scale; v[j*4+1]=t.y*scale; v[j*4+2]=t.z*scale; v[j*4+3]=t.w*scale;
    }
    softmax16(v);
#pragma unroll
    for (int j = 0; j < 4; j++)
        *(float4*)(r + j * 4) = make_float4(v[j*4+0], v[j*4+1], v[j*4+2], v[j*4+3]);
}

__global__ void final_fused(const float* __restrict__ e1, const float* __restrict__ acc,
                            const float* __restrict__ accB, const float* __restrict__ e3,
                            const float* __restrict__ wk, float* __restrict__ out) {
    float w0 = wk[96], w2 = wk[97];
    int row = blockIdx.x * 8 + (threadIdx.x >> 5);
    int lane = threadIdx.x & 31;
    size_t base = (size_t)row * 512 + lane * 16;
    float a[16], c[16], v[16];
#pragma unroll
    for (int j = 0; j < 4; j++) {
        float4 t = *(const float4*)(e1 + base + j * 4);
        a[j*4+0]=t.x; a[j*4+1]=t.y; a[j*4+2]=t.z; a[j*4+3]=t.w;
        float4 u = *(const float4*)(e3 + base + j * 4);
        c[j*4+0]=u.x; c[j*4+1]=u.y; c[j*4+2]=u.z; c[j*4+3]=u.w;
    }
    softmax16(a);
    softmax16(c);
#pragma unroll
    for (int j = 0; j < 4; j++) {
        float4 b = *(const float4*)(acc + base + j * 4);
        float4 bb = *(const float4*)(accB + base + j * 4);
        v[j*4+0] = w0*a[j*4+0] + b.x + bb.x + w2*c[j*4+0];
        v[j*4+1] = w0*a[j*4+1] + b.y + bb.y + w2*c[j*4+1];
        v[j*4+2] = w0*a[j*4+2] + b.z + bb.z + w2*c[j*4+2];
        v[j*4+3] = w0*a[j*4+3] + b.w + bb.w + w2*c[j*4+3];
    }
    softmax16(v);
#pragma unroll
    for (int j = 0; j < 4; j++)
        *(float4*)(out + base + j * 4) = make_float4(v[j*4+0], v[j*4+1], v[j*4+2], v[j*4+3]);
}

// ------------------------------- host side -----------------------------------
static inline void* symaddr(const void* sym) {
    void* p = nullptr;
    cudaGetSymbolAddress(&p, sym);
    return p;
}

extern "C" void kernel_launch(void* const* d_in, const int* in_sizes, int n_in,
                              void* d_out, int out_size) {
    const float *x_d, *x_q;
    const int *ei_d, *ei_q;
    if (in_sizes[1] == 2 * EDM) {
        x_d = (const float*)d_in[0]; ei_d = (const int*)d_in[1];
        x_q = (const float*)d_in[2]; ei_q = (const int*)d_in[3];
    } else {
        x_d = (const float*)d_in[0]; x_q = (const float*)d_in[1];
        ei_d = (const int*)d_in[2]; ei_q = (const int*)d_in[3];
    }
    const float* W1 = (const float*)d_in[6];  const float* b1 = (const float*)d_in[7];
    const float* W2 = (const float*)d_in[8];  const float* b2 = (const float*)d_in[9];
    const float* W3 = (const float*)d_in[10]; const float* b3 = (const float*)d_in[11];
    const float* Wn[3] = {(const float*)d_in[12], (const float*)d_in[17], (const float*)d_in[22]};
    const float* Vn[3] = {(const float*)d_in[13], (const float*)d_in[18], (const float*)d_in[23]};
    const float* bn[3] = {(const float*)d_in[14], (const float*)d_in[19], (const float*)d_in[24]};
    const float* cw1 = (const float*)d_in[15];
    const float* cw2 = (const float*)d_in[20];
    const float* cw3 = (const float*)d_in[25];
    const float* w_end = (const float*)d_in[27];

    cudaFuncSetAttribute(hmma_gemm<0>, cudaFuncAttributeMaxDynamicSharedMemorySize, HG_SMEM);
    cudaFuncSetAttribute(hmma_gemm<1>, cudaFuncAttributeMaxDynamicSharedMemorySize, HG_SMEM);
    cudaFuncSetAttribute(score_hmma,   cudaFuncAttributeMaxDynamicSharedMemorySize, SC_SMEM);
    cudaFuncSetAttribute(ntn_fused_kern, cudaFuncAttributeMaxDynamicSharedMemorySize, NTN_SMEM);

    int* p_indeg = (int*)symaddr(g_indeg);
    int* p_rows = (int*)symaddr(g_rows);     float* p_dinv = (float*)symaddr(g_dinv);
    int* p_cols = (int*)symaddr(g_cols);     float* p_vals = (float*)symaddr(g_vals);
    float* p_xw = (float*)symaddr(g_xw);
    float* p_att3 = (float*)symaddr(g_att3);
    float* p_lq3 = (float*)symaddr(g_lq3);   float* p_ld3 = (float*)symaddr(g_ld3);
    float* p_e1 = (float*)symaddr(g_e1);     float* p_e3 = (float*)symaddr(g_e3);
    float* p_acc = (float*)symaddr(g_acc);   float* p_accB = (float*)symaddr(g_accB);
    float* p_wk = (float*)symaddr(g_wk);
    __nv_bfloat16* p_hallh = (__nv_bfloat16*)symaddr(g_hallh);
    __nv_bfloat16* p_halll = (__nv_bfloat16*)symaddr(g_halll);
    __nv_bfloat16* p_qwh3 = (__nv_bfloat16*)symaddr(g_qwh3);
    __nv_bfloat16* p_qwl3 = (__nv_bfloat16*)symaddr(g_qwl3);
    __nv_bfloat16* p_xh = (__nv_bfloat16*)symaddr(g_xh);
    __nv_bfloat16* p_xl = (__nv_bfloat16*)symaddr(g_xl);
    __nv_bfloat16* p_w1th = (__nv_bfloat16*)symaddr(g_w1th);
    __nv_bfloat16* p_w1tl = (__nv_bfloat16*)symaddr(g_w1tl);
    __nv_bfloat16* p_w2th = (__nv_bfloat16*)symaddr(g_w2th);
    __nv_bfloat16* p_w2tl = (__nv_bfloat16*)symaddr(g_w2tl);
    __nv_bfloat16* p_w3th = (__nv_bfloat16*)symaddr(g_w3th);
    __nv_bfloat16* p_w3tl = (__nv_bfloat16*)symaddr(g_w3tl);
    __nv_bfloat16* p_wnth = (__nv_bfloat16*)symaddr(g_wnth);
    __nv_bfloat16* p_wntl = (__nv_bfloat16*)symaddr(g_wntl);
    float* out = (float*)d_out;

    const int* src_d = ei_d;           const int* dst_d = ei_d + EDM;
    const int* src_q = ei_q;           const int* dst_q = ei_q + EQM;
    const __nv_bfloat16* w_h[3] = {p_w1th, p_w2th, p_w3th};
    const __nv_bfloat16* w_l[3] = {p_w1tl, p_w2tl, p_w3tl};
    const float* bias[3] = {b1, b2, b3};

    prep_all<<<9569, 256>>>(W1, W2, W3, Wn[0], Wn[1], Wn[2], x_d, x_q,
                            cw1, cw2, cw3, w_end,
                            p_w1th, p_w1tl, p_w2th, p_w2tl, p_w3th, p_w3tl,
                            p_wnth, p_wntl, p_xh, p_xl, p_wk);
    csr_build_kern<<<128, 512>>>(src_d, dst_d, src_q, dst_q,
                                 p_indeg, p_rows, p_dinv, p_cols, p_vals);
    for (int l = 0; l < 3; l++) {
        const __nv_bfloat16* Ah = (l == 0) ? p_xh : p_hallh + (size_t)(l - 1) * NALL * DDF;
        const __nv_bfloat16* Al = (l == 0) ? p_xl : p_halll + (size_t)(l - 1) * NALL * DDF;
        hmma_gemm<0><<<dim3(1, NALL / 128, 1), 256, HG_SMEM>>>(
            Ah, Al, w_h[l], w_l[l], p_xw, nullptr, nullptr, 128, 0, 0, 0);
        spmm_gcn<<<NALL * 32 / 256, 256>>>(p_xw, p_rows, p_cols, p_vals, p_indeg, p_dinv,
                                           bias[l],
                                           p_hallh + (size_t)l * NALL * DDF,
                                           p_halll + (size_t)l * NALL * DDF,
                                           Vn[l],
                                           p_lq3 + (size_t)l * NQN * KKN,
                                           p_ld3 + (size_t)l * NDN * KKN, NALL);
    }
    score_hmma<<<dim3(4, BBATCH, 3), 256, SC_SMEM>>>(p_hallh, p_halll, p_att3);
    row_softmax512<<<768, 256>>>(p_att3, 0.08838834764831845f);
    hmma_gemm<1><<<dim3(16, 16, 3), 256, HG_SMEM>>>(
        p_hallh + (size_t)NDN * DDF, p_halll + (size_t)NDN * DDF, p_wnth, p_wntl,
        nullptr, p_qwh3, p_qwl3, 0, (long)NALL * DDF, 2048L * 128, (long)QWS);
    ntn_fused_kern<<<dim3(2, 4, 192), 256, NTN_SMEM>>>(
        p_qwh3, p_qwl3, p_hallh, p_halll, p_lq3, p_ld3,
        bn[0], bn[1], bn[2], p_att3, p_wk, p_e1, p_acc, p_e3, p_accB);
    final_fused<<<256, 256>>>(p_e1, p_acc, p_accB, p_e3, p_wk, out);
}

// round 15
// speedup vs baseline: 1.0717x; 1.0700x over previous
#include <cuda_runtime.h>
#include <cuda_bf16.h>
#include <math.h>
#include <stdint.h>

#define BBATCH 64
#define NQD    32
#define NDD    512
#define DINF   64
#define DDF    128
#define KKN    16
#define NDN    (BBATCH*NDD)      // 32768
#define NQN    (BBATCH*NQD)      // 2048
#define NALL   (NDN+NQN)         // 34816
#define EDM    (NDN*8)           // 262144
#define EQM    (NQN*8)           // 16384
#define EALL   (EDM+EQM)         // 278528
#define ATTS   ((size_t)BBATCH*NQD*NDD)
#define QWS    ((size_t)BBATCH*512*DDF)

// ------------------------- static device scratch ----------------------------
__device__ float g_dinv[NALL];
__device__ int   g_indeg[NALL];
__device__ int   g_rows[NALL];
__device__ int   g_cols[EALL];
__device__ float g_vals[EALL];
__device__ float g_xw[(size_t)NALL*DDF];
__device__ float g_att3[3*ATTS];
__device__ float g_lq3[3*NQN*KKN];
__device__ float g_ld3[3*NDN*KKN];
__device__ float g_e1[ATTS];
__device__ float g_e3[ATTS];
__device__ float g_acc[ATTS];
__device__ float g_accB[ATTS];
__device__ float g_wk[128];
__device__ __nv_bfloat16 g_hallh[(size_t)3*NALL*DDF];
__device__ __nv_bfloat16 g_halll[(size_t)3*NALL*DDF];
__device__ __nv_bfloat16 g_qwh3[3*QWS];
__device__ __nv_bfloat16 g_qwl3[3*QWS];
__device__ __nv_bfloat16 g_xh[(size_t)NALL*DDF], g_xl[(size_t)NALL*DDF];
__device__ __nv_bfloat16 g_w1th[DDF*DDF], g_w1tl[DDF*DDF];
__device__ __nv_bfloat16 g_w2th[DDF*DDF], g_w2tl[DDF*DDF];
__device__ __nv_bfloat16 g_w3th[DDF*DDF], g_w3tl[DDF*DDF];
__device__ __nv_bfloat16 g_wnth[(size_t)3*KKN*DDF*DDF], g_wntl[(size_t)3*KKN*DDF*DDF];
__device__ __nv_bfloat16 g_vnh[3*KKN*256], g_vnl[3*KKN*256];

// --------------------------- PTX helpers -------------------------------------
__device__ __forceinline__ uint32_t smem_u32(const void* p) {
    uint32_t a;
    asm("{ .reg .u64 t; cvta.to.shared.u64 t, %1; cvt.u32.u64 %0, t; }" : "=r"(a) : "l"(p));
    return a;
}
#define LDSM_X4(r, a) \
    asm volatile("ldmatrix.sync.aligned.m8n8.x4.shared.b16 {%0,%1,%2,%3}, [%4];" \
        : "=r"((r)[0]), "=r"((r)[1]), "=r"((r)[2]), "=r"((r)[3]) : "r"(a))
#define LDSM_X2(r, a) \
    asm volatile("ldmatrix.sync.aligned.m8n8.x2.shared.b16 {%0,%1}, [%2];" \
        : "=r"((r)[0]), "=r"((r)[1]) : "r"(a))
#define MMA16816(d, a, b) \
    asm volatile("mma.sync.aligned.m16n8k16.row.col.f32.bf16.bf16.f32 " \
        "{%0,%1,%2,%3},{%4,%5,%6,%7},{%8,%9},{%0,%1,%2,%3};" \
        : "+f"((d)[0]), "+f"((d)[1]), "+f"((d)[2]), "+f"((d)[3]) \
        : "r"((a)[0]), "r"((a)[1]), "r"((a)[2]), "r"((a)[3]), "r"((b)[0]), "r"((b)[1]))

// =================== fused prep: weights + inputs + wk + Vn ==================
__global__ void prep_all(
    const float* __restrict__ W1, const float* __restrict__ W2, const float* __restrict__ W3,
    const float* __restrict__ Wn1, const float* __restrict__ Wn2, const float* __restrict__ Wn3,
    const float* __restrict__ Vn1, const float* __restrict__ Vn2, const float* __restrict__ Vn3,
    const float* __restrict__ x_d, const float* __restrict__ x_q,
    const float* __restrict__ cw1, const float* __restrict__ cw2, const float* __restrict__ cw3,
    const float* __restrict__ w_end,
    __nv_bfloat16* __restrict__ w1th, __nv_bfloat16* __restrict__ w1tl,
    __nv_bfloat16* __restrict__ w2th, __nv_bfloat16* __restrict__ w2tl,
    __nv_bfloat16* __restrict__ w3th, __nv_bfloat16* __restrict__ w3tl,
    __nv_bfloat16* __restrict__ wnth, __nv_bfloat16* __restrict__ wntl,
    __nv_bfloat16* __restrict__ xh, __nv_bfloat16* __restrict__ xl,
    __nv_bfloat16* __restrict__ vnh, __nv_bfloat16* __restrict__ vnl,
    float* __restrict__ wk) {
    __shared__ float ts[32][33];
    const int blk = blockIdx.x, tid = threadIdx.x;
    if (blk < 800) {
        const float* src; __nv_bfloat16 *oh, *ol; int k, t2;
        if (blk < 16)      { src = W2; oh = w2th; ol = w2tl; k = 0; t2 = blk; }
        else if (blk < 32) { src = W3; oh = w3th; ol = w3tl; k = 0; t2 = blk - 16; }
        else {
            int t = blk - 32, l = t >> 8, rem = t & 255;
            k = rem >> 4; t2 = rem & 15;
            src = (l == 0) ? Wn1 : (l == 1) ? Wn2 : Wn3;
            oh = wnth + (size_t)l * 2048 * 128; ol = wntl + (size_t)l * 2048 * 128;
        }
        int e0 = (t2 & 3) * 32, d0 = (t2 >> 2) * 32;
        int tx = tid & 31, ty = tid >> 5;
        const float* ink = src + (size_t)k * 16384;
#pragma unroll
        for (int j = 0; j < 32; j += 8)
            ts[ty + j][tx] = ink[(size_t)(d0 + ty + j) * 128 + e0 + tx];
        __syncthreads();
#pragma unroll
        for (int j = 0; j < 32; j += 8) {
            float v = ts[tx][ty + j];
            size_t o = ((size_t)k * 128 + e0 + ty + j) * 128 + d0 + tx;
            __nv_bfloat16 h = __float2bfloat16(v);
            oh[o] = h;
            ol[o] = __float2bfloat16(v - __bfloat162float(h));
        }
    } else if (blk < 864) {
        int i = (blk - 800) * 256 + tid;
        int e = i >> 7, d = i & 127;
        float v = (d < 64) ? W1[d * 128 + e] : 0.f;
        __nv_bfloat16 h = __float2bfloat16(v);
        w1th[i] = h;
        w1tl[i] = __float2bfloat16(v - __bfloat162float(h));
    } else if (blk < 864 + 8192) {
        int i = (blk - 864) * 256 + tid;
        int node = i >> 6, c = i & 63;
        float v = x_d[i];
        __nv_bfloat16 h = __float2bfloat16(v);
        size_t o = (size_t)node * 128 + c;
        xh[o] = h; xl[o] = __float2bfloat16(v - __bfloat162float(h));
        xh[o + 64] = __float2bfloat16(0.f);
        xl[o + 64] = __float2bfloat16(0.f);
    } else if (blk < 864 + 8192 + 512) {
        int i = (blk - 864 - 8192) * 256 + tid;
        int node = NDN + (i >> 6), c = i & 63;
        float v = x_q[i];
        __nv_bfloat16 h = __float2bfloat16(v);
        size_t o = (size_t)node * 128 + c;
        xh[o] = h; xl[o] = __float2bfloat16(v - __bfloat162float(h));
        xh[o + 64] = __float2bfloat16(0.f);
        xl[o + 64] = __float2bfloat16(0.f);
    } else if (blk == 9568) {
        int k = tid;
        if (k < 16) {
            wk[k]      = cw1[k];                              wk[16 + k] = 0.f;
            wk[32 + k] = w_end[1] * cw2[k] + w_end[19 + k];   wk[48 + k] = 0.f;
            wk[64 + k] = cw3[k];
            wk[80 + k] = w_end[3 + k] + w_end[35 + k];
        }
        if (k == 0) { wk[96] = w_end[0]; wk[97] = w_end[2]; }
    } else {
        int i = (blk - 9569) * 256 + tid;   // 12288 = 3*16*256
        if (i < 12288) {
            int l = i >> 12, rem = i & 4095;
            const float* Vn = (l == 0) ? Vn1 : (l == 1) ? Vn2 : Vn3;
            float v = Vn[rem];
            __nv_bfloat16 h = __float2bfloat16(v);
            vnh[i] = h;
            vnl[i] = __float2bfloat16(v - __bfloat162float(h));
        }
    }
}

// ========== CSR build: one CTA per graph, all atomics in shared mem ==========
__global__ __launch_bounds__(512) void csr_build_kern(
    const int* __restrict__ src_d, const int* __restrict__ dst_d,
    const int* __restrict__ src_q, const int* __restrict__ dst_q,
    int* __restrict__ indeg, int* __restrict__ rows, float* __restrict__ dinv,
    int* __restrict__ cols, float* __restrict__ vals) {
    __shared__ int sdeg[512];
    __shared__ int sfill[512];
    __shared__ int srow[512];
    __shared__ float sdinv[512];
    const int g = blockIdx.x, t = threadIdx.x;
    int nper, eper, nodebase, lbase, ebase, gEdgeBase, goff;
    const int *src, *dst;
    if (g < 64) {
        nper = 512; eper = 4096; nodebase = g * 512; lbase = g * 512;
        ebase = g * 4096; gEdgeBase = g * 4096; goff = 0;
        src = src_d; dst = dst_d;
    } else {
        int gq = g - 64;
        nper = 32; eper = 256; nodebase = NDN + gq * 32; lbase = gq * 32;
        ebase = gq * 256; gEdgeBase = EDM + gq * 256; goff = NDN;
        src = src_q; dst = dst_q;
    }
    if (t < nper) { sdeg[t] = 0; sfill[t] = 0; }
    __syncthreads();
    for (int e = t; e < eper; e += 512)
        atomicAdd(&sdeg[dst[ebase + e] - lbase], 1);
    __syncthreads();
    int v = (t < nper) ? sdeg[t] : 0;
    srow[t] = v;
    __syncthreads();
    for (int off = 1; off < 512; off <<= 1) {
        int x = (t >= off) ? srow[t - off] : 0;
        __syncthreads();
        srow[t] += x;
        __syncthreads();
    }
    if (t < nper) {
        int excl = srow[t] - v;
        srow[t] = excl;
        float di = rsqrtf((float)v + 1.0f);
        sdinv[t] = di;
        indeg[nodebase + t] = v;
        rows[nodebase + t] = gEdgeBase + excl;
        dinv[nodebase + t] = di;
    }
    __syncthreads();
    for (int e = t; e < eper; e += 512) {
        int s = src[ebase + e] - lbase, d2 = dst[ebase + e] - lbase;
        int p = atomicAdd(&sfill[d2], 1);
        int idx = gEdgeBase + srow[d2] + p;
        cols[idx] = s + lbase + goff;
        vals[idx] = sdinv[s] * sdinv[d2];
    }
}

// ------ GCN aggregation: pure gather + split-bf16 emit (Vn dot moved out) ----
__global__ void spmm_gcn(const float* __restrict__ h, const int* __restrict__ rows,
                         const int* __restrict__ cols, const float* __restrict__ vals,
                         const int* __restrict__ indeg, const float* __restrict__ dinv,
                         const float* __restrict__ bias,
                         __nv_bfloat16* __restrict__ oh, __nv_bfloat16* __restrict__ ol,
                         int N) {
    const unsigned FULL = 0xffffffffu;
    int t = blockIdx.x * blockDim.x + threadIdx.x;
    int node = t >> 5, lane = t & 31;
    if (node >= N) return;
    float di = dinv[node];
    float self = di * di;
    float4 hv = *(const float4*)(h + (size_t)node * 128 + lane * 4);
    float ax = self * hv.x, ay = self * hv.y, az = self * hv.z, aw = self * hv.w;
    int r0 = rows[node], cnt = indeg[node];
    int cnt32 = cnt < 32 ? cnt : 32;
    int myc = 0; float myw = 0.f;
    if (lane < cnt32) { myc = __ldg(&cols[r0 + lane]); myw = __ldg(&vals[r0 + lane]); }
    int e = 0;
    for (; e + 4 <= cnt32; e += 4) {
        int sA = __shfl_sync(FULL, myc, e + 0); float wA = __shfl_sync(FULL, myw, e + 0);
        int sB = __shfl_sync(FULL, myc, e + 1); float wB = __shfl_sync(FULL, myw, e + 1);
        int sC = __shfl_sync(FULL, myc, e + 2); float wC = __shfl_sync(FULL, myw, e + 2);
        int sD = __shfl_sync(FULL, myc, e + 3); float wD = __shfl_sync(FULL, myw, e + 3);
        float4 a0 = *(const float4*)(h + (size_t)sA * 128 + lane * 4);
        float4 a1 = *(const float4*)(h + (size_t)sB * 128 + lane * 4);
        float4 a2 = *(const float4*)(h + (size_t)sC * 128 + lane * 4);
        float4 a3 = *(const float4*)(h + (size_t)sD * 128 + lane * 4);
        ax += wA * a0.x; ay += wA * a0.y; az += wA * a0.z; aw += wA * a0.w;
        ax += wB * a1.x; ay += wB * a1.y; az += wB * a1.z; aw += wB * a1.w;
        ax += wC * a2.x; ay += wC * a2.y; az += wC * a2.z; aw += wC * a2.w;
        ax += wD * a3.x; ay += wD * a3.y; az += wD * a3.z; aw += wD * a3.w;
    }
    for (; e < cnt32; e++) {
        int s = __shfl_sync(FULL, myc, e); float w = __shfl_sync(FULL, myw, e);
        float4 n4 = *(const float4*)(h + (size_t)s * 128 + lane * 4);
        ax += w * n4.x; ay += w * n4.y; az += w * n4.z; aw += w * n4.w;
    }
    for (; e < cnt; e++) {
        int s = __ldg(&cols[r0 + e]);
        float w = __ldg(&vals[r0 + e]);
        float4 n4 = *(const float4*)(h + (size_t)s * 128 + lane * 4);
        ax += w * n4.x; ay += w * n4.y; az += w * n4.z; aw += w * n4.w;
    }
    float4 b4 = *(const float4*)(bias + lane * 4);
    float4 o;
    o.x = fmaxf(ax + b4.x, 0.f); o.y = fmaxf(ay + b4.y, 0.f);
    o.z = fmaxf(az + b4.z, 0.f); o.w = fmaxf(aw + b4.w, 0.f);
    __nv_bfloat162 h01 = __floats2bfloat162_rn(o.x, o.y);
    __nv_bfloat162 h23 = __floats2bfloat162_rn(o.z, o.w);
    *(__nv_bfloat162*)(oh + (size_t)node * 128 + lane * 4)     = h01;
    *(__nv_bfloat162*)(oh + (size_t)node * 128 + lane * 4 + 2) = h23;
    *(__nv_bfloat162*)(ol + (size_t)node * 128 + lane * 4) =
        __floats2bfloat162_rn(o.x - __bfloat162float(h01.x), o.y - __bfloat162float(h01.y));
    *(__nv_bfloat162*)(ol + (size_t)node * 128 + lane * 4 + 2) =
        __floats2bfloat162_rn(o.z - __bfloat162float(h23.x), o.w - __bfloat162float(h23.y));
}

// ===== lq/ld via HMMA: [node,16] = feat[node,128] @ VnSliceT, z = level ======
#define LQ_AH 0
#define LQ_AL 34816
#define LQ_BH 69632
#define LQ_BL 73984
#define LQ_SMEM 78336
__global__ __launch_bounds__(256, 2) void lqld_hmma(
    const __nv_bfloat16* __restrict__ Hh, const __nv_bfloat16* __restrict__ Hl,
    const __nv_bfloat16* __restrict__ vnh, const __nv_bfloat16* __restrict__ vnl,
    float* __restrict__ lq3, float* __restrict__ ld3) {
    extern __shared__ char smem[];
    const int tid = threadIdx.x;
    const int warp = tid >> 5, lane = tid & 31;
    const int l = blockIdx.z;
    const int mt0 = blockIdx.y * 128;
    const int isQ = (mt0 >= NDN);
    const __nv_bfloat16* Ah = Hh + (size_t)l * NALL * DDF;
    const __nv_bfloat16* Al = Hl + (size_t)l * NALL * DDF;
    const int off = isQ ? 0 : 128;   // lq uses Vn[:, :128], ld uses Vn[:, 128:]
    float* out = isQ ? (lq3 + (size_t)l * NQN * 16 + (size_t)(mt0 - NDN) * 16)
                     : (ld3 + (size_t)l * NDN * 16 + (size_t)mt0 * 16);
    __nv_bfloat16* sAh = (__nv_bfloat16*)(smem + LQ_AH);
    __nv_bfloat16* sAl = (__nv_bfloat16*)(smem + LQ_AL);
    __nv_bfloat16* sBh = (__nv_bfloat16*)(smem + LQ_BH);
    __nv_bfloat16* sBl = (__nv_bfloat16*)(smem + LQ_BL);

    for (int i = tid; i < 2048; i += 256) {
        int row = i >> 4, c8 = (i & 15) << 3;
        size_t g = ((size_t)(mt0 + row)) * 128 + c8;
        *(uint4*)(sAh + row * 136 + c8) = *(const uint4*)(Ah + g);
        *(uint4*)(sAl + row * 136 + c8) = *(const uint4*)(Al + g);
    }
    if (tid < 256) {
        int row = tid >> 4, c8 = (tid & 15) << 3;
        size_t g = (size_t)l * 4096 + row * 256 + off + c8;
        *(uint4*)(sBh + row * 136 + c8) = *(const uint4*)(vnh + g);
        *(uint4*)(sBl + row * 136 + c8) = *(const uint4*)(vnl + g);
    }
    __syncthreads();

    const int m0 = warp * 16;
    uint32_t sa_h = smem_u32(sAh) + ((m0 + (lane & 15)) * 136 + ((lane & 16) ? 8 : 0)) * 2;
    uint32_t sa_l = sa_h + (LQ_AL - LQ_AH);
    uint32_t sb_h = smem_u32(sBh) + (((lane & 7)) * 136 + ((lane & 8) ? 8 : 0)) * 2;
    uint32_t sb_l = sb_h + (LQ_BL - LQ_BH);

    float acc[2][4];
#pragma unroll
    for (int ch = 0; ch < 2; ch++)
#pragma unroll
        for (int j = 0; j < 4; j++) acc[ch][j] = 0.f;

#pragma unroll
    for (int s = 0; s < 8; s++) {
        uint32_t RAh[4], RAl[4];
        LDSM_X4(RAh, sa_h + s * 32);
        LDSM_X4(RAl, sa_l + s * 32);
#pragma unroll
        for (int ch = 0; ch < 2; ch++) {
            uint32_t RBh[2], RBl[2];
            LDSM_X2(RBh, sb_h + ch * 2176 + s * 32);
            LDSM_X2(RBl, sb_l + ch * 2176 + s * 32);
            MMA16816(acc[ch], RAh, RBh);
            MMA16816(acc[ch], RAh, RBl);
            MMA16816(acc[ch], RAl, RBh);
        }
    }
    const int g = lane >> 2, t2 = lane & 3;
#pragma unroll
    for (int ch = 0; ch < 2; ch++) {
        int k = ch * 8 + t2 * 2;
        *(float2*)(out + (size_t)(m0 + g) * 16 + k) =
            make_float2(acc[ch][0], acc[ch][1]);
        *(float2*)(out + (size_t)(m0 + g + 8) * 16 + k) =
            make_float2(acc[ch][2], acc[ch][3]);
    }
}

// ===================== generic split-bf16 HMMA GEMM ==========================
#define HG_AH 0
#define HG_AL 34816
#define HG_BH 69632
#define HG_BL 104448
#define HG_SMEM 139264

template<int EPI>
__global__ __launch_bounds__(256, 1) void hmma_gemm(
    const __nv_bfloat16* __restrict__ Ah, const __nv_bfloat16* __restrict__ Al,
    const __nv_bfloat16* __restrict__ Bh, const __nv_bfloat16* __restrict__ Bl,
    float* __restrict__ outF, __nv_bfloat16* __restrict__ oh,
    __nv_bfloat16* __restrict__ ol, int ldC,
    long zsA, long zsB, long zsO) {
    extern __shared__ char smem[];
    const int tid = threadIdx.x;
    const int warp = tid >> 5, lane = tid & 31;
    const int mt0 = blockIdx.y * 128, nt0 = blockIdx.x * 128;
    const long za = (long)blockIdx.z * zsA, zb = (long)blockIdx.z * zsB;
    const long zo = (long)blockIdx.z * zsO;
    __nv_bfloat16* sAh = (__nv_bfloat16*)(smem + HG_AH);
    __nv_bfloat16* sAl = (__nv_bfloat16*)(smem + HG_AL);
    __nv_bfloat16* sBh = (__nv_bfloat16*)(smem + HG_BH);
    __nv_bfloat16* sBl = (__nv_bfloat16*)(smem + HG_BL);

    for (int i = tid; i < 2048; i += 256) {
        int row = i >> 4, c8 = (i & 15) << 3;
        size_t g = za + ((size_t)(mt0 + row)) * 128 + c8;
        *(uint4*)(sAh + row * 136 + c8) = *(const uint4*)(Ah + g);
        *(uint4*)(sAl + row * 136 + c8) = *(const uint4*)(Al + g);
        size_t gb = zb + ((size_t)(nt0 + row)) * 128 + c8;
        *(uint4*)(sBh + row * 136 + c8) = *(const uint4*)(Bh + gb);
        *(uint4*)(sBl + row * 136 + c8) = *(const uint4*)(Bl + gb);
    }
    __syncthreads();

    const int wy = warp >> 1, wx = warp & 1;
    uint32_t sa_h = smem_u32(sAh) + ((wy * 32 + (lane & 15)) * 136 + ((lane & 16) ? 8 : 0)) * 2;
    uint32_t sa_l = sa_h + (HG_AL - HG_AH);
    uint32_t sb_h = smem_u32(sBh) + ((wx * 64 + (lane & 7)) * 136 + ((lane & 8) ? 8 : 0)) * 2;
    uint32_t sb_l = sb_h + (HG_BL - HG_BH);

    float acc[2][8][4];
#pragma unroll
    for (int mt = 0; mt < 2; mt++)
#pragma unroll
        for (int ch = 0; ch < 8; ch++)
#pragma unroll
            for (int j = 0; j < 4; j++) acc[mt][ch][j] = 0.f;

#pragma unroll
    for (int s = 0; s < 8; s++) {
        uint32_t RAh[2][4], RAl[2][4];
        LDSM_X4(RAh[0], sa_h + s * 32);
        LDSM_X4(RAh[1], sa_h + 4352 + s * 32);
        LDSM_X4(RAl[0], sa_l + s * 32);
        LDSM_X4(RAl[1], sa_l + 4352 + s * 32);
#pragma unroll
        for (int ch = 0; ch < 8; ch++) {
            uint32_t RBh[2], RBl[2];
            LDSM_X2(RBh, sb_h + ch * 2176 + s * 32);
            LDSM_X2(RBl, sb_l + ch * 2176 + s * 32);
#pragma unroll
            for (int mt = 0; mt < 2; mt++) {
                MMA16816(acc[mt][ch], RAh[mt], RBh);
                MMA16816(acc[mt][ch], RAh[mt], RBl);
                MMA16816(acc[mt][ch], RAl[mt], RBh);
            }
        }
    }

    const int g = lane >> 2, t2 = lane & 3;
#pragma unroll
    for (int mt = 0; mt < 2; mt++) {
#pragma unroll
        for (int ch = 0; ch < 8; ch++) {
            int r = mt0 + wy * 32 + mt * 16 + g;
            int c = nt0 + wx * 64 + ch * 8 + t2 * 2;
            if (EPI == 0) {
                *(float2*)(outF + (size_t)r * ldC + c) =
                    make_float2(acc[mt][ch][0], acc[mt][ch][1]);
                *(float2*)(outF + (size_t)(r + 8) * ldC + c) =
                    make_float2(acc[mt][ch][2], acc[mt][ch][3]);
            } else {
                int kk = c >> 7, e = c & 127;
#pragma unroll
                for (int half = 0; half < 2; half++) {
                    int rr = r + half * 8;
                    int bb = rr >> 5, q = rr & 31;
                    size_t orow = zo + ((size_t)bb * 512 + q * 16 + kk) * 128 + e;
                    float v0 = acc[mt][ch][half * 2], v1 = acc[mt][ch][half * 2 + 1];
                    __nv_bfloat162 ph = __floats2bfloat162_rn(v0, v1);
                    *(__nv_bfloat162*)(oh + orow) = ph;
                    *(__nv_bfloat162*)(ol + orow) = __floats2bfloat162_rn(
                        v0 - __bfloat162float(ph.x), v1 - __bfloat162float(ph.y));
                }
            }
        }
    }
}

// ----------- attention scores via HMMA (z = level) ---------------------------
#define SC_AH 0
#define SC_AL 8704
#define SC_BH 17408
#define SC_BL 52224
#define SC_SMEM 87040
__global__ __launch_bounds__(256, 2) void score_hmma(
    const __nv_bfloat16* __restrict__ Hh, const __nv_bfloat16* __restrict__ Hl,
    float* __restrict__ S) {
    extern __shared__ char smem[];
    const int tid = threadIdx.x;
    const int warp = tid >> 5, lane = tid & 31;
    const int b = blockIdx.y, nt0 = blockIdx.x * 128, l = blockIdx.z;
    const size_t zq = (size_t)l * NALL * DDF + (size_t)NDN * DDF;
    const size_t zd = (size_t)l * NALL * DDF;
    float* Sl = S + (size_t)l * ATTS;
    __nv_bfloat16* sAh = (__nv_bfloat16*)(smem + SC_AH);
    __nv_bfloat16* sAl = (__nv_bfloat16*)(smem + SC_AL);
    __nv_bfloat16* sBh = (__nv_bfloat16*)(smem + SC_BH);
    __nv_bfloat16* sBl = (__nv_bfloat16*)(smem + SC_BL);

    for (int i = tid; i < 512; i += 256) {
        int row = i >> 4, c8 = (i & 15) << 3;
        size_t g = zq + ((size_t)b * 32 + row) * 128 + c8;
        *(uint4*)(sAh + row * 136 + c8) = *(const uint4*)(Hh + g);
        *(uint4*)(sAl + row * 136 + c8) = *(const uint4*)(Hl + g);
    }
    for (int i = tid; i < 2048; i += 256) {
        int row = i >> 4, c8 = (i & 15) << 3;
        size_t g = zd + ((size_t)b * 512 + nt0 + row) * 128 + c8;
        *(uint4*)(sBh + row * 136 + c8) = *(const uint4*)(Hh + g);
        *(uint4*)(sBl + row * 136 + c8) = *(const uint4*)(Hl + g);
    }
    __syncthreads();

    uint32_t sa_h = smem_u32(sAh) + (((lane & 15)) * 136 + ((lane & 16) ? 8 : 0)) * 2;
    uint32_t sa_l = sa_h + (SC_AL - SC_AH);
    uint32_t sb_h = smem_u32(sBh) + ((warp * 16 + (lane & 7)) * 136 + ((lane & 8) ? 8 : 0)) * 2;
    uint32_t sb_l = sb_h + (SC_BL - SC_BH);

    float acc[2][2][4];
#pragma unroll
    for (int mt = 0; mt < 2; mt++)
#pragma unroll
        for (int ch = 0; ch < 2; ch++)
#pragma unroll
            for (int j = 0; j < 4; j++) acc[mt][ch][j] = 0.f;

#pragma unroll
    for (int s = 0; s < 8; s++) {
        uint32_t RAh[2][4], RAl[2][4];
        LDSM_X4(RAh[0], sa_h + s * 32);
        LDSM_X4(RAh[1], sa_h + 4352 + s * 32);
        LDSM_X4(RAl[0], sa_l + s * 32);
        LDSM_X4(RAl[1], sa_l + 4352 + s * 32);
#pragma unroll
        for (int ch = 0; ch < 2; ch++) {
            uint32_t RBh[2], RBl[2];
            LDSM_X2(RBh, sb_h + ch * 2176 + s * 32);
            LDSM_X2(RBl, sb_l + ch * 2176 + s * 32);
#pragma unroll
            for (int mt = 0; mt < 2; mt++) {
                MMA16816(acc[mt][ch], RAh[mt], RBh);
                MMA16816(acc[mt][ch], RAh[mt], RBl);
                MMA16816(acc[mt][ch], RAl[mt], RBh);
            }
        }
    }
    const int g = lane >> 2, t2 = lane & 3;
#pragma unroll
    for (int mt = 0; mt < 2; mt++)
#pragma unroll
        for (int ch = 0; ch < 2; ch++) {
            int r = mt * 16 + g;
            int n = nt0 + warp * 16 + ch * 8 + t2 * 2;
            *(float2*)(Sl + ((size_t)b * 32 + r) * 512 + n) =
                make_float2(acc[mt][ch][0], acc[mt][ch][1]);
            *(float2*)(Sl + ((size_t)b * 32 + r + 8) * 512 + n) =
                make_float2(acc[mt][ch][2], acc[mt][ch][3]);
        }
}

// ====== fused NTN level kernel, z = l*64 + b; A-tile reused over 4 n-tiles ===
#define OFF_AH 0
#define OFF_AL 34816
#define OFF_BH 69632
#define OFF_BL 87040
#define OFF_LD 104448
#define OFF_LQ 108544
#define OFF_WK 109056
#define OFF_BN 109184
#define NTN_SMEM 109248

__global__ __launch_bounds__(256, 2) void ntn_fused_kern(
    const __nv_bfloat16* __restrict__ Ah3, const __nv_bfloat16* __restrict__ Al3,
    const __nv_bfloat16* __restrict__ Bh3, const __nv_bfloat16* __restrict__ Bl3,
    const float* __restrict__ lq3, const float* __restrict__ ld3,
    const float* __restrict__ bn1, const float* __restrict__ bn2,
    const float* __restrict__ bn3, const float* __restrict__ att3,
    const float* __restrict__ wk,
    float* __restrict__ e1, float* __restrict__ acc2, float* __restrict__ e3,
    float* __restrict__ accB) {
    extern __shared__ char smem[];
    const int tid = threadIdx.x;
    const int warp = tid >> 5, lane = tid & 31;
    const int z = blockIdx.z, l = z >> 6, b = z & 63;
    const int mt = blockIdx.y;
    const int hasB = (l == 2);
    const __nv_bfloat16* Ah = Ah3 + (size_t)l * QWS;
    const __nv_bfloat16* Al = Al3 + (size_t)l * QWS;
    const __nv_bfloat16* Bh = Bh3 + (size_t)l * NALL * DDF;
    const __nv_bfloat16* Bl = Bl3 + (size_t)l * NALL * DDF;
    const float* lq = lq3 + (size_t)l * NQN * KKN;
    const float* ld = ld3 + (size_t)l * NDN * KKN;
    const float* bn = (l == 0) ? bn1 : (l == 1) ? bn2 : bn3;
    const float* att = att3 + (size_t)l * ATTS;
    float* outA = (l == 0) ? e1 : (l == 1) ? acc2 : e3;
    const int wkofs = l * 32;

    __nv_bfloat16* sAh = (__nv_bfloat16*)(smem + OFF_AH);
    __nv_bfloat16* sAl = (__nv_bfloat16*)(smem + OFF_AL);
    __nv_bfloat16* sBh = (__nv_bfloat16*)(smem + OFF_BH);
    __nv_bfloat16* sBl = (__nv_bfloat16*)(smem + OFF_BL);
    float* s_ld = (float*)(smem + OFF_LD);
    float* s_lq = (float*)(smem + OFF_LQ);
    float* s_wk = (float*)(smem + OFF_WK);
    float* s_bn = (float*)(smem + OFF_BN);

    for (int i = tid; i < 2048; i += 256) {
        int row = i >> 4, c8 = (i & 15) << 3;
        size_t g = ((size_t)b * 512 + (size_t)mt * 128 + row) * 128 + c8;
        *(uint4*)(sAh + row * 136 + c8) = *(const uint4*)(Ah + g);
        *(uint4*)(sAl + row * 136 + c8) = *(const uint4*)(Al + g);
    }
    if (tid < 128) s_lq[tid] = lq[((size_t)b * 32 + mt * 8) * 16 + tid];
    if (tid < 32) s_wk[tid] = wk[wkofs + tid];
    if (tid < 16) s_bn[tid] = bn[tid];

    const int m0 = warp * 16;
    uint32_t sa_h = smem_u32(sAh) + ((m0 + (lane & 15)) * 136 + ((lane & 16) ? 8 : 0)) * 2;
    uint32_t sa_l = sa_h + (OFF_BH - OFF_AL);
    uint32_t sb_h = smem_u32(sBh) + ((lane & 7) * 136 + ((lane & 8) ? 8 : 0)) * 2;
    uint32_t sb_l = sb_h + (OFF_LD - OFF_BL);

    const int q = mt * 8 + warp;
    const int k0 = lane >> 2;
    const int c2 = (lane & 3) * 2;

#pragma unroll 1
    for (int it = 0; it < 4; it++) {
        const int nt = blockIdx.x * 4 + it;
        if (it > 0) __syncthreads();
        for (int i = tid; i < 1024; i += 256) {
            int row = i >> 4, c8 = (i & 15) << 3;
            size_t g = ((size_t)b * 512 + (size_t)nt * 64 + row) * 128 + c8;
            *(uint4*)(sBh + row * 136 + c8) = *(const uint4*)(Bh + g);
            *(uint4*)(sBl + row * 136 + c8) = *(const uint4*)(Bl + g);
        }
        for (int i = tid; i < 256; i += 256)
            ((float4*)s_ld)[i] = ((const float4*)(ld + ((size_t)b * 512 + (size_t)nt * 64) * 16))[i];
        __syncthreads();

        float acc[8][4];
#pragma unroll
        for (int c = 0; c < 8; c++)
#pragma unroll
            for (int j = 0; j < 4; j++) acc[c][j] = 0.f;

#pragma unroll
        for (int s = 0; s < 8; s++) {
            uint32_t RAh[4], RAl[4];
            LDSM_X4(RAh, sa_h + s * 32);
            LDSM_X4(RAl, sa_l + s * 32);
#pragma unroll
            for (int ch = 0; ch < 8; ch++) {
                uint32_t RBh[2], RBl[2];
                LDSM_X2(RBh, sb_h + ch * 2176 + s * 32);
                LDSM_X2(RBl, sb_l + ch * 2176 + s * 32);
                MMA16816(acc[ch], RAh, RBh);
                MMA16816(acc[ch], RAh, RBl);
                MMA16816(acc[ch], RAl, RBh);
            }
        }

        const float lq0 = s_lq[warp * 16 + k0] + s_bn[k0];
        const float lq1 = s_lq[warp * 16 + k0 + 8] + s_bn[k0 + 8];
        const float al0 = s_wk[k0], al1 = s_wk[k0 + 8];
        const float be0 = s_wk[16 + k0], be1 = s_wk[16 + k0 + 8];

#pragma unroll
        for (int ch = 0; ch < 8; ch++) {
            int n0 = ch * 8 + c2;
            float sg00 = 1.f / (1.f + __expf(-(acc[ch][0] + lq0 + s_ld[n0 * 16 + k0])));
            float sg01 = 1.f / (1.f + __expf(-(acc[ch][1] + lq0 + s_ld[(n0 + 1) * 16 + k0])));
            float sg10 = 1.f / (1.f + __expf(-(acc[ch][2] + lq1 + s_ld[n0 * 16 + k0 + 8])));
            float sg11 = 1.f / (1.f + __expf(-(acc[ch][3] + lq1 + s_ld[(n0 + 1) * 16 + k0 + 8])));
            float u0 = al0 * sg00 + al1 * sg10;
            float u1 = al0 * sg01 + al1 * sg11;
#pragma unroll
            for (int off = 4; off < 32; off <<= 1) {
                u0 += __shfl_xor_sync(0xffffffffu, u0, off);
                u1 += __shfl_xor_sync(0xffffffffu, u1, off);
            }
            float v0 = 0.f, v1 = 0.f;
            if (hasB) {
                v0 = be0 * sg00 + be1 * sg10;
                v1 = be0 * sg01 + be1 * sg11;
#pragma unroll
                for (int off = 4; off < 32; off <<= 1) {
                    v0 += __shfl_xor_sync(0xffffffffu, v0, off);
                    v1 += __shfl_xor_sync(0xffffffffu, v1, off);
                }
            }
            if (lane < 4) {
                size_t o = ((size_t)b * 32 + q) * 512 + (size_t)nt * 64 + ch * 8 + lane * 2;
                float a0 = att[o], a1 = att[o + 1];
                outA[o]     = u0 * a0;
                outA[o + 1] = u1 * a1;
                if (hasB) {
                    accB[o]     = v0 * a0;
                    accB[o + 1] = v1 * a1;
                }
            }
        }
    }
}

// ----------------------------- softmaxes -------------------------------------
__device__ __forceinline__ float warp_max(float v) {
#pragma unroll
    for (int o = 16; o > 0; o >>= 1) v = fmaxf(v, __shfl_xor_sync(0xffffffffu, v, o));
    return v;
}
__device__ __forceinline__ float warp_sum(float v) {
#pragma unroll
    for (int o = 16; o > 0; o >>= 1) v += __shfl_xor_sync(0xffffffffu, v, o);
    return v;
}
__device__ __forceinline__ void softmax16(float* v) {
    float m = -1e30f;
#pragma unroll
    for (int i = 0; i < 16; i++) m = fmaxf(m, v[i]);
    m = warp_max(m);
    float s = 0.f;
#pragma unroll
    for (int i = 0; i < 16; i++) { v[i] = __expf(v[i] - m); s += v[i]; }
    s = warp_sum(s);
    float inv = 1.f / s;
#pragma unroll
    for (int i = 0; i < 16; i++) v[i] *= inv;
}

__global__ void row_softmax512(float* __restrict__ p, float scale) {
    int row = blockIdx.x * 8 + (threadIdx.x >> 5);
    int lane = threadIdx.x & 31;
    float* r = p + (size_t)row * 512 + lane * 16;
    float v[16];
#pragma unroll
    for (int j = 0; j < 4; j++) {
        float4 t = *(float4*)(r + j * 4);
        v[j*4+0]=t.x*scale; v[j*4+1]=t.y*scale; v[j*4+2]=t.z*scale; v[j*4+3]=t.w*scale;
    }
    softmax16(v);
#pragma unroll
    for (int j = 0; j < 4; j++)
        *(float4*)(r + j * 4) = make_float4(v[j*4+0], v[j*4+1], v[j*4+2], v[j*4+3]);
}

__global__ void final_fused(const float* __restrict__ e1, const float* __restrict__ acc,
                            const float* __restrict__ accB, const float* __restrict__ e3,
                            const float* __restrict__ wk, float* __restrict__ out) {
    float w0 = wk[96], w2 = wk[97];
    int row = blockIdx.x * 8 + (threadIdx.x >> 5);
    int lane = threadIdx.x & 31;
    size_t base = (size_t)row * 512 + lane * 16;
    float a[16], c[16], v[16];
#pragma unroll
    for (int j = 0; j < 4; j++) {
        float4 t = *(const float4*)(e1 + base + j * 4);
        a[j*4+0]=t.x; a[j*4+1]=t.y; a[j*4+2]=t.z; a[j*4+3]=t.w;
        float4 u = *(const float4*)(e3 + base + j * 4);
        c[j*4+0]=u.x; c[j*4+1]=u.y; c[j*4+2]=u.z; c[j*4+3]=u.w;
    }
    softmax16(a);
    softmax16(c);
#pragma unroll
    for (int j = 0; j < 4; j++) {
        float4 b = *(const float4*)(acc + base + j * 4);
        float4 bb = *(const float4*)(accB + base + j * 4);
        v[j*4+0] = w0*a[j*4+0] + b.x + bb.x + w2*c[j*4+0];
        v[j*4+1] = w0*a[j*4+1] + b.y + bb.y + w2*c[j*4+1];
        v[j*4+2] = w0*a[j*4+2] + b.z + bb.z + w2*c[j*4+2];
        v[j*4+3] = w0*a[j*4+3] + b.w + bb.w + w2*c[j*4+3];
    }
    softmax16(v);
#pragma unroll
    for (int j = 0; j < 4; j++)
        *(float4*)(out + base + j * 4) = make_float4(v[j*4+0], v[j*4+1], v[j*4+2], v[j*4+3]);
}

// ------------------------------- host side -----------------------------------
static inline void* symaddr(const void* sym) {
    void* p = nullptr;
    cudaGetSymbolAddress(&p, sym);
    return p;
}

extern "C" void kernel_launch(void* const* d_in, const int* in_sizes, int n_in,
                              void* d_out, int out_size) {
    const float *x_d, *x_q;
    const int *ei_d, *ei_q;
    if (in_sizes[1] == 2 * EDM) {
        x_d = (const float*)d_in[0]; ei_d = (const int*)d_in[1];
        x_q = (const float*)d_in[2]; ei_q = (const int*)d_in[3];
    } else {
        x_d = (const float*)d_in[0]; x_q = (const float*)d_in[1];
        ei_d = (const int*)d_in[2]; ei_q = (const int*)d_in[3];
    }
    const float* W1 = (const float*)d_in[6];  const float* b1 = (const float*)d_in[7];
    const float* W2 = (const float*)d_in[8];  const float* b2 = (const float*)d_in[9];
    const float* W3 = (const float*)d_in[10]; const float* b3 = (const float*)d_in[11];
    const float* Wn[3] = {(const float*)d_in[12], (const float*)d_in[17], (const float*)d_in[22]};
    const float* Vn[3] = {(const float*)d_in[13], (const float*)d_in[18], (const float*)d_in[23]};
    const float* bn[3] = {(const float*)d_in[14], (const float*)d_in[19], (const float*)d_in[24]};
    const float* cw1 = (const float*)d_in[15];
    const float* cw2 = (const float*)d_in[20];
    const float* cw3 = (const float*)d_in[25];
    const float* w_end = (const float*)d_in[27];

    cudaFuncSetAttribute(hmma_gemm<0>, cudaFuncAttributeMaxDynamicSharedMemorySize, HG_SMEM);
    cudaFuncSetAttribute(hmma_gemm<1>, cudaFuncAttributeMaxDynamicSharedMemorySize, HG_SMEM);
    cudaFuncSetAttribute(score_hmma,   cudaFuncAttributeMaxDynamicSharedMemorySize, SC_SMEM);
    cudaFuncSetAttribute(lqld_hmma,    cudaFuncAttributeMaxDynamicSharedMemorySize, LQ_SMEM);
    cudaFuncSetAttribute(ntn_fused_kern, cudaFuncAttributeMaxDynamicSharedMemorySize, NTN_SMEM);

    int* p_indeg = (int*)symaddr(g_indeg);
    int* p_rows = (int*)symaddr(g_rows);     float* p_dinv = (float*)symaddr(g_dinv);
    int* p_cols = (int*)symaddr(g_cols);     float* p_vals = (float*)symaddr(g_vals);
    float* p_xw = (float*)symaddr(g_xw);
    float* p_att3 = (float*)symaddr(g_att3);
    float* p_lq3 = (float*)symaddr(g_lq3);   float* p_ld3 = (float*)symaddr(g_ld3);
    float* p_e1 = (float*)symaddr(g_e1);     float* p_e3 = (float*)symaddr(g_e3);
    float* p_acc = (float*)symaddr(g_acc);   float* p_accB = (float*)symaddr(g_accB);
    float* p_wk = (float*)symaddr(g_wk);
    __nv_bfloat16* p_hallh = (__nv_bfloat16*)symaddr(g_hallh);
    __nv_bfloat16* p_halll = (__nv_bfloat16*)symaddr(g_halll);
    __nv_bfloat16* p_qwh3 = (__nv_bfloat16*)symaddr(g_qwh3);
    __nv_bfloat16* p_qwl3 = (__nv_bfloat16*)symaddr(g_qwl3);
    __nv_bfloat16* p_xh = (__nv_bfloat16*)symaddr(g_xh);
    __nv_bfloat16* p_xl = (__nv_bfloat16*)symaddr(g_xl);
    __nv_bfloat16* p_w1th = (__nv_bfloat16*)symaddr(g_w1th);
    __nv_bfloat16* p_w1tl = (__nv_bfloat16*)symaddr(g_w1tl);
    __nv_bfloat16* p_w2th = (__nv_bfloat16*)symaddr(g_w2th);
    __nv_bfloat16* p_w2tl = (__nv_bfloat16*)symaddr(g_w2tl);
    __nv_bfloat16* p_w3th = (__nv_bfloat16*)symaddr(g_w3th);
    __nv_bfloat16* p_w3tl = (__nv_bfloat16*)symaddr(g_w3tl);
    __nv_bfloat16* p_wnth = (__nv_bfloat16*)symaddr(g_wnth);
    __nv_bfloat16* p_wntl = (__nv_bfloat16*)symaddr(g_wntl);
    __nv_bfloat16* p_vnh = (__nv_bfloat16*)symaddr(g_vnh);
    __nv_bfloat16* p_vnl = (__nv_bfloat16*)symaddr(g_vnl);
    float* out = (float*)d_out;

    const int* src_d = ei_d;           const int* dst_d = ei_d + EDM;
    const int* src_q = ei_q;           const int* dst_q = ei_q + EQM;
    const __nv_bfloat16* w_h[3] = {p_w1th, p_w2th, p_w3th};
    const __nv_bfloat16* w_l[3] = {p_w1tl, p_w2tl, p_w3tl};
    const float* bias[3] = {b1, b2, b3};

    prep_all<<<9617, 256>>>(W1, W2, W3, Wn[0], Wn[1], Wn[2], Vn[0], Vn[1], Vn[2],
                            x_d, x_q, cw1, cw2, cw3, w_end,
                            p_w1th, p_w1tl, p_w2th, p_w2tl, p_w3th, p_w3tl,
                            p_wnth, p_wntl, p_xh, p_xl, p_vnh, p_vnl, p_wk);
    csr_build_kern<<<128, 512>>>(src_d, dst_d, src_q, dst_q,
                                 p_indeg, p_rows, p_dinv, p_cols, p_vals);
    for (int l = 0; l < 3; l++) {
        const __nv_bfloat16* Ah = (l == 0) ? p_xh : p_hallh + (size_t)(l - 1) * NALL * DDF;
        const __nv_bfloat16* Al = (l == 0) ? p_xl : p_halll + (size_t)(l - 1) * NALL * DDF;
        hmma_gemm<0><<<dim3(1, NALL / 128, 1), 256, HG_SMEM>>>(
            Ah, Al, w_h[l], w_l[l], p_xw, nullptr, nullptr, 128, 0, 0, 0);
        spmm_gcn<<<NALL * 32 / 256, 256>>>(p_xw, p_rows, p_cols, p_vals, p_indeg, p_dinv,
                                           bias[l],
                                           p_hallh + (size_t)l * NALL * DDF,
                                           p_halll + (size_t)l * NALL * DDF, NALL);
    }
    lqld_hmma<<<dim3(1, NALL / 128, 3), 256, LQ_SMEM>>>(p_hallh, p_halll, p_vnh, p_vnl,
                                                        p_lq3, p_ld3);
    score_hmma<<<dim3(4, BBATCH, 3), 256, SC_SMEM>>>(p_hallh, p_halll, p_att3);
    row_softmax512<<<768, 256>>>(p_att3, 0.08838834764831845f);
    hmma_gemm<1><<<dim3(16, 16, 3), 256, HG_SMEM>>>(
        p_hallh + (size_t)NDN * DDF, p_halll + (size_t)NDN * DDF, p_wnth, p_wntl,
        nullptr, p_qwh3, p_qwl3, 0, (long)NALL * DDF, 2048L * 128, (long)QWS);
    ntn_fused_kern<<<dim3(2, 4, 192), 256, NTN_SMEM>>>(
        p_qwh3, p_qwl3, p_hallh, p_halll, p_lq3, p_ld3,
        bn[0], bn[1], bn[2], p_att3, p_wk, p_e1, p_acc, p_e3, p_accB);
    final_fused<<<256, 256>>>(p_e1, p_acc, p_accB, p_e3, p_wk, out);
}